// round 11
// baseline (speedup 1.0000x reference)
#include <cuda_runtime.h>
#include <cuda_bf16.h>
#include <cuda_fp16.h>
#include <cstdint>

#define B_   4
#define S_   2048
#define E_   1024
#define H_   16
#define D_   64
#define QD_  1024
#define KD_  768
#define VD_  768
#define M_   (B_ * S_)          // 8192
#define BH_  (B_ * H_)          // 64

// ---------------- device scratch (no allocations allowed) ----------------
__device__ __align__(16) __nv_bfloat16 g_Ahi[M_ * E_];
__device__ __align__(16) __nv_bfloat16 g_Alo[M_ * E_];
__device__ __align__(16) __nv_bfloat16 g_Whi[E_ * E_];
__device__ __align__(16) __nv_bfloat16 g_Wlo[E_ * E_];
__device__ __align__(16) __half g_Wohi[E_ * E_];
__device__ __align__(16) __half g_Wolo[E_ * E_];
__device__ __align__(16) __half g_qhi[BH_ * S_ * D_];
__device__ __align__(16) __half g_khi[BH_ * S_ * D_];
__device__ __align__(16) __half g_klo[BH_ * S_ * D_];
__device__ __align__(16) __half g_vhi[BH_ * S_ * D_];
__device__ __align__(16) __half g_vlo[BH_ * S_ * D_];
__device__ __align__(16) __half g_vthi[BH_ * D_ * S_];
__device__ __align__(16) __half g_vtlo[BH_ * D_ * S_];
__device__ __align__(16) __half g_ctxh[M_ * E_];
__device__ float g_psum[BH_ * 16 * S_];
__device__ float g_rinv[BH_ * S_];

// ======================= helpers ============================
__device__ __forceinline__ uint32_t smem_u32(const void* p) {
    uint32_t a;
    asm("{ .reg .u64 t; cvta.to.shared.u64 t, %1; cvt.u32.u64 %0, t; }"
        : "=r"(a) : "l"(p));
    return a;
}
__device__ __forceinline__ void cp16(uint32_t dst, const void* src) {
    asm volatile("cp.async.cg.shared.global [%0], [%1], 16;" :: "r"(dst), "l"(src));
}
#define LDSM4(R, addr) \
    asm volatile("ldmatrix.sync.aligned.m8n8.x4.shared.b16 {%0,%1,%2,%3}, [%4];" \
                 : "=r"((R)[0]), "=r"((R)[1]), "=r"((R)[2]), "=r"((R)[3]) : "r"(addr))
#define MMA_BF16(c, a, b0, b1) \
    asm volatile("mma.sync.aligned.m16n8k16.row.col.f32.bf16.bf16.f32 " \
                 "{%0,%1,%2,%3}, {%4,%5,%6,%7}, {%8,%9}, {%0,%1,%2,%3};" \
                 : "+f"((c)[0]), "+f"((c)[1]), "+f"((c)[2]), "+f"((c)[3]) \
                 : "r"((a)[0]), "r"((a)[1]), "r"((a)[2]), "r"((a)[3]), "r"(b0), "r"(b1))
#define MMA_F16(c, a, b0, b1) \
    asm volatile("mma.sync.aligned.m16n8k16.row.col.f32.f16.f16.f32 " \
                 "{%0,%1,%2,%3}, {%4,%5,%6,%7}, {%8,%9}, {%0,%1,%2,%3};" \
                 : "+f"((c)[0]), "+f"((c)[1]), "+f"((c)[2]), "+f"((c)[3]) \
                 : "r"((a)[0]), "r"((a)[1]), "r"((a)[2]), "r"((a)[3]), "r"(b0), "r"(b1))

__device__ __forceinline__ float fast_exp(float x) {
    float t = x * 1.44269504088896341f;
    t = fmaxf(t, -125.0f);
    float r = t + 12582912.0f;
    int   n = __float_as_int(r) - 0x4B400000;
    float f = t - (r - 12582912.0f);
    float p = 1.33336498e-3f;
    p = fmaf(p, f, 9.61011466e-3f);
    p = fmaf(p, f, 5.55036595e-2f);
    p = fmaf(p, f, 2.40226510e-1f);
    p = fmaf(p, f, 6.93147182e-1f);
    p = fmaf(p, f, 1.0f);
    return __int_as_float((n + 127) << 23) * p;
}

// fp32 pair -> fp16 hi/lo pair at half2-element index o (lo optional)
__device__ __forceinline__ void store_hl_h2(
    void* Ohi, void* Olo, size_t o, float x0, float x1)
{
    __half2 hh = __floats2half2_rn(x0, x1);
    ((__half2*)Ohi)[o] = hh;
    if (Olo) {
        float l0 = x0 - __half2float(__low2half(hh));
        float l1 = x1 - __half2float(__high2half(hh));
        ((__half2*)Olo)[o] = __floats2half2_rn(l0, l1);
    }
}

// ================= generic split tensor-core GEMM ========================
// MODE 0: bf16 3-term  (A = bf16 hi/lo gmem)         C = Ah·Bh + Ah·Bl + Al·Bh
// MODE 1: fp16 2-term  (A = fp16 gmem)               C = A·Bh + A·Bl
// MODE 2: fp16 2-term  (A = fp32 e-values; in-load p = e*rinv[row], p written
//                       back to C (fp32) and converted to fp16 for the MMA)
// B: [N,K] 16-bit hi/lo row-major.  Tiles 128 x BN, BK=32, 2-stage cp.async.
// EPI 0: fp32 C (+bias, alpha, batch strides)
// EPI 1: fp16 hi/lo head-major [bh][s][d] (+bias); Olo optional
// EPI 2: fp16 row-major [token][E] at col (z%zdiv)*64 + col
// EPI 3: scores: write e=exp(alpha*acc) to C + per-(row,colblock) sums to gps
template<int BN, int MODE, int EPI>
__global__ __launch_bounds__(256) void hilo_gemm(
    const void* __restrict__ Ahi_, const void* __restrict__ Alo_,
    const void* __restrict__ Bhi_, const void* __restrict__ Blo_,
    const float* __restrict__ bias, float* __restrict__ C,
    void* __restrict__ Ohi, void* __restrict__ Olo,
    const float* __restrict__ rinv, float* __restrict__ gps,
    int K, int ldA, int ldB, int ldC,
    long long strideA, long long strideB,
    long long sCo, long long sCi, int zdiv, float alpha)
{
    constexpr int NI     = BN / 16;
    constexpr int SSA    = 128 * 80;
    constexpr int ATILES = (MODE == 0) ? 2 : 1;
    constexpr int BOF    = BN * 80;
    constexpr int SS     = ATILES * SSA + 2 * BOF;
    extern __shared__ __align__(16) char smem[];
    const uint32_t sbase = smem_u32(smem);
    __shared__ float s_r[128];

    const int tid  = threadIdx.x;
    const int lane = tid & 31;
    const int wid  = tid >> 5;
    const int m0w  = (wid >> 1) * 32;
    const int n0w  = (wid & 1) * (BN / 2);
    const int m0   = blockIdx.y * 128;
    const int n0   = blockIdx.x * BN;
    const size_t z = blockIdx.z;

    const uint16_t* Ah16 = nullptr;
    const uint16_t* Al16 = nullptr;
    const float*    Af   = nullptr;
    float*          AfW  = nullptr;
    if (MODE == 2) {
        Af  = (const float*)Ahi_ + z * strideA + (size_t)m0 * ldA;
        AfW = C + z * strideA + (size_t)m0 * ldA;
        if (tid < 128) s_r[tid] = rinv[z * S_ + m0 + tid];
        __syncthreads();
    } else {
        Ah16 = (const uint16_t*)Ahi_ + z * strideA + (size_t)m0 * ldA;
        if (MODE == 0)
            Al16 = (const uint16_t*)Alo_ + z * strideA + (size_t)m0 * ldA;
    }
    const uint16_t* Bh = (const uint16_t*)Bhi_ + z * strideB + (size_t)n0 * ldB;
    const uint16_t* Bl = (const uint16_t*)Blo_ + z * strideB + (size_t)n0 * ldB;

    const int T = K / 32;
    float acc[2][NI][4];
    #pragma unroll
    for (int i = 0; i < 2; i++)
        #pragma unroll
        for (int j = 0; j < NI; j++)
            #pragma unroll
            for (int q = 0; q < 4; q++) acc[i][j][q] = 0.0f;

    auto load_stage = [&](int it) {
        const int st = it & 1;
        const int k0 = it * 32;
        const uint32_t sb = sbase + st * SS;
        #pragma unroll
        for (int c = tid; c < BN * 8; c += 256) {
            int tile = (c >= BN * 4) ? 1 : 0;
            int cc   = c - tile * BN * 4;
            int r    = cc >> 2, seg = cc & 3;
            const uint16_t* src = (tile ? Bl : Bh) + (size_t)r * ldB + k0 + seg * 8;
            cp16(sb + ATILES * SSA + tile * BOF + r * 80 + seg * 16, src);
        }
        if (MODE == 0) {
            #pragma unroll
            for (int c = tid; c < 1024; c += 256) {
                int tile = c >> 9;
                int r = (c >> 2) & 127, seg = c & 3;
                const uint16_t* src = (tile ? Al16 : Ah16) + (size_t)r * ldA + k0 + seg * 8;
                cp16(sb + tile * SSA + r * 80 + seg * 16, src);
            }
        } else if (MODE == 1) {
            #pragma unroll
            for (int c = tid; c < 512; c += 256) {
                int r = c >> 2, seg = c & 3;
                cp16(sb + r * 80 + seg * 16, Ah16 + (size_t)r * ldA + k0 + seg * 8);
            }
        } else {
            char* sp = smem + st * SS;
            #pragma unroll
            for (int c = tid; c < 1024; c += 256) {
                int r = c >> 3, seg = c & 7;
                float4 v = *(const float4*)(Af + (size_t)r * ldA + k0 + seg * 4);
                const float rv = s_r[r];
                v.x *= rv; v.y *= rv; v.z *= rv; v.w *= rv;
                *(float4*)(AfW + (size_t)r * ldA + k0 + seg * 4) = v;  // weights out
                __half2 h01 = __floats2half2_rn(v.x, v.y);
                __half2 h23 = __floats2half2_rn(v.z, v.w);
                *(uint32_t*)(sp + r * 80 + seg * 8)     = *(uint32_t*)&h01;
                *(uint32_t*)(sp + r * 80 + seg * 8 + 4) = *(uint32_t*)&h23;
            }
        }
    };

    load_stage(0);
    asm volatile("cp.async.commit_group;" ::: "memory");

    for (int it = 0; it < T; it++) {
        if (it + 1 < T) {
            load_stage(it + 1);
            asm volatile("cp.async.commit_group;" ::: "memory");
            asm volatile("cp.async.wait_group 1;" ::: "memory");
        } else {
            asm volatile("cp.async.wait_group 0;" ::: "memory");
        }
        __syncthreads();

        const uint32_t sA = sbase + (it & 1) * SS;
        const uint32_t sB = sA + ATILES * SSA;
        #pragma unroll
        for (int kk = 0; kk < 2; kk++) {
            uint32_t ah[2][4], al[2][4];
            #pragma unroll
            for (int mi = 0; mi < 2; mi++) {
                uint32_t addr = sA + ((m0w + mi * 16 + (lane & 15)) * 40
                                      + kk * 16 + ((lane >> 4) << 3)) * 2;
                LDSM4(ah[mi], addr);
                if (MODE == 0) LDSM4(al[mi], addr + SSA);
            }
            uint32_t bh[NI][2], bl[NI][2];
            #pragma unroll
            for (int nj = 0; nj < NI / 2; nj++) {
                uint32_t row = n0w + nj * 16 + (lane & 7) + ((lane >> 4) << 3);
                uint32_t col = kk * 16 + (((lane >> 3) & 1) << 3);
                uint32_t addr = sB + (row * 40 + col) * 2;
                uint32_t t4[4];
                LDSM4(t4, addr);
                bh[2 * nj][0] = t4[0]; bh[2 * nj][1] = t4[1];
                bh[2 * nj + 1][0] = t4[2]; bh[2 * nj + 1][1] = t4[3];
                LDSM4(t4, addr + BOF);
                bl[2 * nj][0] = t4[0]; bl[2 * nj][1] = t4[1];
                bl[2 * nj + 1][0] = t4[2]; bl[2 * nj + 1][1] = t4[3];
            }
            #pragma unroll
            for (int mi = 0; mi < 2; mi++)
                #pragma unroll
                for (int ni = 0; ni < NI; ni++) {
                    if (MODE == 0) {
                        MMA_BF16(acc[mi][ni], ah[mi], bh[ni][0], bh[ni][1]);
                        MMA_BF16(acc[mi][ni], ah[mi], bl[ni][0], bl[ni][1]);
                        MMA_BF16(acc[mi][ni], al[mi], bh[ni][0], bh[ni][1]);
                    } else {
                        MMA_F16(acc[mi][ni], ah[mi], bh[ni][0], bh[ni][1]);
                        MMA_F16(acc[mi][ni], ah[mi], bl[ni][0], bl[ni][1]);
                    }
                }
        }
        __syncthreads();
    }

    // ---------------- epilogue ----------------
    if (EPI == 0) {
        float* Cz = C + (z / zdiv) * sCo + (z % zdiv) * sCi;
        #pragma unroll
        for (int mi = 0; mi < 2; mi++)
            #pragma unroll
            for (int ni = 0; ni < NI; ni++) {
                int row = m0 + m0w + mi * 16 + (lane >> 2);
                int col = n0 + n0w + ni * 8 + ((lane & 3) << 1);
                float b0 = bias ? __ldg(bias + col) : 0.0f;
                float b1 = bias ? __ldg(bias + col + 1) : 0.0f;
                Cz[(size_t)row * ldC + col]           = acc[mi][ni][0] * alpha + b0;
                Cz[(size_t)row * ldC + col + 1]       = acc[mi][ni][1] * alpha + b1;
                Cz[(size_t)(row + 8) * ldC + col]     = acc[mi][ni][2] * alpha + b0;
                Cz[(size_t)(row + 8) * ldC + col + 1] = acc[mi][ni][3] * alpha + b1;
            }
    } else if (EPI == 1) {
        #pragma unroll
        for (int mi = 0; mi < 2; mi++)
            #pragma unroll
            for (int ni = 0; ni < NI; ni++) {
                int row = m0 + m0w + mi * 16 + (lane >> 2);
                int col = n0 + n0w + ni * 8 + ((lane & 3) << 1);
                float b0 = bias ? __ldg(bias + col) : 0.0f;
                float b1 = bias ? __ldg(bias + col + 1) : 0.0f;
                int h = col >> 6, d = col & 63;
                #pragma unroll
                for (int rr = 0; rr < 2; rr++) {
                    int r = row + rr * 8;
                    int b = r >> 11, s = r & 2047;
                    size_t o = ((((size_t)(b * 16 + h)) * S_ + s) * D_ + d) >> 1;
                    store_hl_h2(Ohi, Olo, o,
                                acc[mi][ni][rr * 2 + 0] + b0,
                                acc[mi][ni][rr * 2 + 1] + b1);
                }
            }
    } else if (EPI == 2) {
        const int b = (int)z / zdiv, h = (int)z % zdiv;
        #pragma unroll
        for (int mi = 0; mi < 2; mi++)
            #pragma unroll
            for (int ni = 0; ni < NI; ni++) {
                int srow = m0 + m0w + mi * 16 + (lane >> 2);
                int col  = n0 + n0w + ni * 8 + ((lane & 3) << 1);
                #pragma unroll
                for (int rr = 0; rr < 2; rr++) {
                    int s = srow + rr * 8;
                    size_t token = (size_t)b * S_ + s;
                    size_t o = (token * E_ + h * D_ + col) >> 1;
                    ((__half2*)Ohi)[o] =
                        __floats2half2_rn(acc[mi][ni][rr * 2 + 0],
                                          acc[mi][ni][rr * 2 + 1]);
                }
            }
    } else {
        // EPI == 3: scores — write e = exp(alpha*acc), accumulate row sums
        __shared__ float ps_s[128][2];
        float* Cz = C + z * sCo;
        float rs[2][2] = {{0.0f, 0.0f}, {0.0f, 0.0f}};
        #pragma unroll
        for (int mi = 0; mi < 2; mi++)
            #pragma unroll
            for (int ni = 0; ni < NI; ni++) {
                int row = m0 + m0w + mi * 16 + (lane >> 2);
                int col = n0 + n0w + ni * 8 + ((lane & 3) << 1);
                float e0 = fast_exp(acc[mi][ni][0] * alpha);
                float e1 = fast_exp(acc[mi][ni][1] * alpha);
                float e2 = fast_exp(acc[mi][ni][2] * alpha);
                float e3 = fast_exp(acc[mi][ni][3] * alpha);
                Cz[(size_t)row * ldC + col]           = e0;
                Cz[(size_t)row * ldC + col + 1]       = e1;
                Cz[(size_t)(row + 8) * ldC + col]     = e2;
                Cz[(size_t)(row + 8) * ldC + col + 1] = e3;
                rs[mi][0] += e0 + e1;
                rs[mi][1] += e2 + e3;
            }
        #pragma unroll
        for (int mi = 0; mi < 2; mi++)
            #pragma unroll
            for (int rr = 0; rr < 2; rr++) {
                float v = rs[mi][rr];
                v += __shfl_xor_sync(0xFFFFFFFFu, v, 1);
                v += __shfl_xor_sync(0xFFFFFFFFu, v, 2);
                rs[mi][rr] = v;
            }
        if ((lane & 3) == 0) {
            #pragma unroll
            for (int mi = 0; mi < 2; mi++)
                #pragma unroll
                for (int rr = 0; rr < 2; rr++)
                    ps_s[m0w + mi * 16 + (lane >> 2) + rr * 8][wid & 1] = rs[mi][rr];
        }
        __syncthreads();
        if (tid < 128) {
            size_t o = ((size_t)z * gridDim.x + blockIdx.x) * (size_t)S_ + m0 + tid;
            gps[o] = ps_s[tid][0] + ps_s[tid][1];
        }
    }
}

// ---------------- combine: rinv = 1 / sum of 16 col-block partials -------
__global__ __launch_bounds__(256) void combine_kernel(
    const float* __restrict__ gps, float* __restrict__ rinv)
{
    int g = blockIdx.x * 256 + threadIdx.x;        // [BH*2048)
    int bh = g >> 11, r = g & 2047;
    const float* ps = gps + (size_t)bh * 16 * S_ + r;
    float s = 0.0f;
    #pragma unroll
    for (int jb = 0; jb < 16; jb++) s += ps[(size_t)jb * S_];
    rinv[g] = 1.0f / s;
}

// ================= conversions ===========================================
__global__ __launch_bounds__(256) void conv_hilo4_kernel(
    const float4* __restrict__ in, __nv_bfloat162* __restrict__ hi,
    __nv_bfloat162* __restrict__ lo, int n4)
{
    int i = blockIdx.x * 256 + threadIdx.x;
    if (i < n4) {
        float4 v = in[i];
        __nv_bfloat162 h01 = __floats2bfloat162_rn(v.x, v.y);
        __nv_bfloat162 h23 = __floats2bfloat162_rn(v.z, v.w);
        hi[2 * i]     = h01;
        hi[2 * i + 1] = h23;
        lo[2 * i]     = __floats2bfloat162_rn(v.x - __bfloat162float(h01.x),
                                              v.y - __bfloat162float(h01.y));
        lo[2 * i + 1] = __floats2bfloat162_rn(v.z - __bfloat162float(h23.x),
                                              v.w - __bfloat162float(h23.y));
    }
}

// W[K,N] fp32 -> Wt[N,K] bf16 hi/lo
__global__ __launch_bounds__(256) void transconv_bf_kernel(
    const float* __restrict__ W, __nv_bfloat16* __restrict__ hi,
    __nv_bfloat16* __restrict__ lo, int K, int N)
{
    __shared__ float t[32][33];
    const int k0 = blockIdx.y * 32, n0 = blockIdx.x * 32;
    const int tx = threadIdx.x & 31, ty = threadIdx.x >> 5;
    #pragma unroll
    for (int i = 0; i < 32; i += 8)
        t[ty + i][tx] = W[(size_t)(k0 + ty + i) * N + n0 + tx];
    __syncthreads();
    #pragma unroll
    for (int i = 0; i < 32; i += 8) {
        float x = t[tx][ty + i];
        __nv_bfloat16 h = __float2bfloat16(x);
        size_t o = (size_t)(n0 + ty + i) * K + k0 + tx;
        hi[o] = h;
        lo[o] = __float2bfloat16(x - __bfloat162float(h));
    }
}

// W[K,N] fp32 -> Wt[N,K] fp16 hi/lo
__global__ __launch_bounds__(256) void transconv_h_kernel(
    const float* __restrict__ W, __half* __restrict__ hi,
    __half* __restrict__ lo, int K, int N)
{
    __shared__ float t[32][33];
    const int k0 = blockIdx.y * 32, n0 = blockIdx.x * 32;
    const int tx = threadIdx.x & 31, ty = threadIdx.x >> 5;
    #pragma unroll
    for (int i = 0; i < 32; i += 8)
        t[ty + i][tx] = W[(size_t)(k0 + ty + i) * N + n0 + tx];
    __syncthreads();
    #pragma unroll
    for (int i = 0; i < 32; i += 8) {
        float x = t[tx][ty + i];
        __half h = __float2half_rn(x);
        size_t o = (size_t)(n0 + ty + i) * K + k0 + tx;
        hi[o] = h;
        lo[o] = __float2half_rn(x - __half2float(h));
    }
}

// [bh][s][d] 16-bit -> [bh][d][s] 16-bit (hi and lo together)
__global__ __launch_bounds__(256) void transpose16_kernel(
    const uint16_t* __restrict__ hi_in, const uint16_t* __restrict__ lo_in,
    uint16_t* __restrict__ hi_out, uint16_t* __restrict__ lo_out)
{
    __shared__ uint16_t th[32][33];
    __shared__ uint16_t tl[32][33];
    const int bh = blockIdx.z;
    const int s0 = blockIdx.x * 32, d0 = blockIdx.y * 32;
    const int tx = threadIdx.x & 31, ty = threadIdx.x >> 5;
    #pragma unroll
    for (int i = 0; i < 32; i += 8) {
        size_t src = ((size_t)bh * S_ + s0 + ty + i) * D_ + d0 + tx;
        th[ty + i][tx] = hi_in[src];
        tl[ty + i][tx] = lo_in[src];
    }
    __syncthreads();
    #pragma unroll
    for (int i = 0; i < 32; i += 8) {
        size_t dst = ((size_t)bh * D_ + d0 + ty + i) * S_ + s0 + tx;
        hi_out[dst] = th[tx][ty + i];
        lo_out[dst] = tl[tx][ty + i];
    }
}

// ---------------- launch ----------------
extern "C" void kernel_launch(void* const* d_in, const int* in_sizes, int n_in,
                              void* d_out, int out_size)
{
    const float* query = (const float*)d_in[0];
    const float* key   = (const float*)d_in[1];
    const float* value = (const float*)d_in[2];
    const float* Wq    = (const float*)d_in[3];
    const float* bq    = (const float*)d_in[4];
    const float* Wk    = (const float*)d_in[5];
    const float* bk    = (const float*)d_in[6];
    const float* Wv    = (const float*)d_in[7];
    const float* bv    = (const float*)d_in[8];
    const float* Wo    = (const float*)d_in[9];
    const float* bo    = (const float*)d_in[10];

    float* out  = (float*)d_out;                 // [B,S,E]
    float* Wbuf = out + (size_t)M_ * E_;         // [B,H,S,S]

    __nv_bfloat16 *ahi, *alo, *whi, *wlo;
    __half *wohi, *wolo, *qhi, *khi, *klo, *vhi, *vlo, *vthi, *vtlo, *ctxh;
    float *gps, *gri;
    cudaGetSymbolAddress((void**)&ahi,  g_Ahi);
    cudaGetSymbolAddress((void**)&alo,  g_Alo);
    cudaGetSymbolAddress((void**)&whi,  g_Whi);
    cudaGetSymbolAddress((void**)&wlo,  g_Wlo);
    cudaGetSymbolAddress((void**)&wohi, g_Wohi);
    cudaGetSymbolAddress((void**)&wolo, g_Wolo);
    cudaGetSymbolAddress((void**)&qhi,  g_qhi);
    cudaGetSymbolAddress((void**)&khi,  g_khi);
    cudaGetSymbolAddress((void**)&klo,  g_klo);
    cudaGetSymbolAddress((void**)&vhi,  g_vhi);
    cudaGetSymbolAddress((void**)&vlo,  g_vlo);
    cudaGetSymbolAddress((void**)&vthi, g_vthi);
    cudaGetSymbolAddress((void**)&vtlo, g_vtlo);
    cudaGetSymbolAddress((void**)&ctxh, g_ctxh);
    cudaGetSymbolAddress((void**)&gps,  g_psum);
    cudaGetSymbolAddress((void**)&gri,  g_rinv);

    const int SMEM_PROJ = 2 * (2 * 128 * 80 + 2 * 128 * 80);  // 81920
    const int SMEM_H16  = 2 * (1 * 128 * 80 + 2 * 128 * 80);  // 61440
    const int SMEM_AV   = 2 * (1 * 128 * 80 + 2 * 64 * 80);   // 40960
    cudaFuncSetAttribute(hilo_gemm<128, 0, 1>,
                         cudaFuncAttributeMaxDynamicSharedMemorySize, SMEM_PROJ);
    cudaFuncSetAttribute(hilo_gemm<128, 1, 3>,
                         cudaFuncAttributeMaxDynamicSharedMemorySize, SMEM_H16);
    cudaFuncSetAttribute(hilo_gemm<128, 1, 0>,
                         cudaFuncAttributeMaxDynamicSharedMemorySize, SMEM_H16);
    cudaFuncSetAttribute(hilo_gemm<64, 2, 2>,
                         cudaFuncAttributeMaxDynamicSharedMemorySize, SMEM_AV);

    // ---- projections (bf16 3-term, write head-major fp16 hi/lo) ----
    conv_hilo4_kernel<<<(M_ * QD_ / 4 + 255) / 256, 256>>>(
        (const float4*)query, (__nv_bfloat162*)ahi, (__nv_bfloat162*)alo, M_ * QD_ / 4);
    transconv_bf_kernel<<<dim3(E_ / 32, QD_ / 32), 256>>>(Wq, whi, wlo, QD_, E_);
    hilo_gemm<128, 0, 1><<<dim3(E_ / 128, M_ / 128, 1), 256, SMEM_PROJ>>>(
        ahi, alo, whi, wlo, bq, nullptr, qhi, nullptr, nullptr, nullptr,
        QD_, QD_, QD_, E_, 0, 0, 0, 0, 1, 1.0f);

    conv_hilo4_kernel<<<(M_ * KD_ / 4 + 255) / 256, 256>>>(
        (const float4*)key, (__nv_bfloat162*)ahi, (__nv_bfloat162*)alo, M_ * KD_ / 4);
    transconv_bf_kernel<<<dim3(E_ / 32, KD_ / 32), 256>>>(Wk, whi, wlo, KD_, E_);
    hilo_gemm<128, 0, 1><<<dim3(E_ / 128, M_ / 128, 1), 256, SMEM_PROJ>>>(
        ahi, alo, whi, wlo, bk, nullptr, khi, klo, nullptr, nullptr,
        KD_, KD_, KD_, E_, 0, 0, 0, 0, 1, 1.0f);

    conv_hilo4_kernel<<<(M_ * VD_ / 4 + 255) / 256, 256>>>(
        (const float4*)value, (__nv_bfloat162*)ahi, (__nv_bfloat162*)alo, M_ * VD_ / 4);
    transconv_bf_kernel<<<dim3(E_ / 32, VD_ / 32), 256>>>(Wv, whi, wlo, VD_, E_);
    hilo_gemm<128, 0, 1><<<dim3(E_ / 128, M_ / 128, 1), 256, SMEM_PROJ>>>(
        ahi, alo, whi, wlo, bv, nullptr, vhi, vlo, nullptr, nullptr,
        VD_, VD_, VD_, E_, 0, 0, 0, 0, 1, 1.0f);

    transpose16_kernel<<<dim3(S_ / 32, D_ / 32, BH_), 256>>>(
        (const uint16_t*)vhi, (const uint16_t*)vlo,
        (uint16_t*)vthi, (uint16_t*)vtlo);

    // ---- scores: fp16 2-term, Wbuf = exp(0.125 * q.k), row-sum partials ----
    hilo_gemm<128, 1, 3><<<dim3(S_ / 128, S_ / 128, BH_), 256, SMEM_H16>>>(
        qhi, nullptr, khi, klo, nullptr, Wbuf, nullptr, nullptr, nullptr, gps,
        D_, D_, D_, S_,
        (long long)S_ * D_, (long long)S_ * D_,
        (long long)S_ * S_, 0, 1, 0.125f);

    // ---- combine partial sums -> rinv ----
    combine_kernel<<<(BH_ * S_) / 256, 256>>>(gps, gri);

    // ---- AV: p = e*rinv in-load (weights written), ctx fp16 out ----
    hilo_gemm<64, 2, 2><<<dim3(1, S_ / 128, BH_), 256, SMEM_AV>>>(
        Wbuf, nullptr, vthi, vtlo, nullptr, Wbuf, ctxh, nullptr, gri, nullptr,
        S_, S_, S_, E_,
        (long long)S_ * S_, (long long)D_ * S_,
        0, 0, 16, 1.0f);

    // ---- output projection: fp16 2-term (A = ctx fp16) ----
    transconv_h_kernel<<<dim3(E_ / 32, E_ / 32), 256>>>(Wo, wohi, wolo, E_, E_);
    hilo_gemm<128, 1, 0><<<dim3(E_ / 128, M_ / 128, 1), 256, SMEM_H16>>>(
        ctxh, nullptr, wohi, wolo, bo, out, nullptr, nullptr, nullptr, nullptr,
        E_, E_, E_, E_, 0, 0, 0, 0, 1, 1.0f);
}

// round 12
// speedup vs baseline: 1.0840x; 1.0840x over previous
#include <cuda_runtime.h>
#include <cuda_bf16.h>
#include <cuda_fp16.h>
#include <cstdint>

#define B_   4
#define S_   2048
#define E_   1024
#define H_   16
#define D_   64
#define QD_  1024
#define KD_  768
#define VD_  768
#define M_   (B_ * S_)          // 8192
#define BH_  (B_ * H_)          // 64

// ---------------- device scratch (no allocations allowed) ----------------
__device__ __align__(16) __nv_bfloat16 g_Ahi[M_ * E_];
__device__ __align__(16) __nv_bfloat16 g_Alo[M_ * E_];
__device__ __align__(16) __nv_bfloat16 g_Whi[E_ * E_];
__device__ __align__(16) __nv_bfloat16 g_Wlo[E_ * E_];
__device__ __align__(16) __half g_Wohi[E_ * E_];
__device__ __align__(16) __half g_Wolo[E_ * E_];
__device__ __align__(16) __half g_qhi[BH_ * S_ * D_];
__device__ __align__(16) __half g_khi[BH_ * S_ * D_];
__device__ __align__(16) __half g_klo[BH_ * S_ * D_];
__device__ __align__(16) __half g_vhi[BH_ * S_ * D_];
__device__ __align__(16) __half g_vlo[BH_ * S_ * D_];
__device__ __align__(16) __half g_vthi[BH_ * D_ * S_];
__device__ __align__(16) __half g_vtlo[BH_ * D_ * S_];
__device__ __align__(16) __half g_ctxh[M_ * E_];
__device__ float g_psum[BH_ * 16 * S_];
__device__ float g_rinv[BH_ * S_];

// ======================= helpers ============================
__device__ __forceinline__ uint32_t smem_u32(const void* p) {
    uint32_t a;
    asm("{ .reg .u64 t; cvta.to.shared.u64 t, %1; cvt.u32.u64 %0, t; }"
        : "=r"(a) : "l"(p));
    return a;
}
__device__ __forceinline__ void cp16(uint32_t dst, const void* src) {
    asm volatile("cp.async.cg.shared.global [%0], [%1], 16;" :: "r"(dst), "l"(src));
}
#define LDSM4(R, addr) \
    asm volatile("ldmatrix.sync.aligned.m8n8.x4.shared.b16 {%0,%1,%2,%3}, [%4];" \
                 : "=r"((R)[0]), "=r"((R)[1]), "=r"((R)[2]), "=r"((R)[3]) : "r"(addr))
#define MMA_BF16(c, a, b0, b1) \
    asm volatile("mma.sync.aligned.m16n8k16.row.col.f32.bf16.bf16.f32 " \
                 "{%0,%1,%2,%3}, {%4,%5,%6,%7}, {%8,%9}, {%0,%1,%2,%3};" \
                 : "+f"((c)[0]), "+f"((c)[1]), "+f"((c)[2]), "+f"((c)[3]) \
                 : "r"((a)[0]), "r"((a)[1]), "r"((a)[2]), "r"((a)[3]), "r"(b0), "r"(b1))
#define MMA_F16(c, a, b0, b1) \
    asm volatile("mma.sync.aligned.m16n8k16.row.col.f32.f16.f16.f32 " \
                 "{%0,%1,%2,%3}, {%4,%5,%6,%7}, {%8,%9}, {%0,%1,%2,%3};" \
                 : "+f"((c)[0]), "+f"((c)[1]), "+f"((c)[2]), "+f"((c)[3]) \
                 : "r"((a)[0]), "r"((a)[1]), "r"((a)[2]), "r"((a)[3]), "r"(b0), "r"(b1))

__device__ __forceinline__ float fast_exp(float x) {
    float t = x * 1.44269504088896341f;
    t = fmaxf(t, -125.0f);
    float r = t + 12582912.0f;
    int   n = __float_as_int(r) - 0x4B400000;
    float f = t - (r - 12582912.0f);
    float p = 1.33336498e-3f;
    p = fmaf(p, f, 9.61011466e-3f);
    p = fmaf(p, f, 5.55036595e-2f);
    p = fmaf(p, f, 2.40226510e-1f);
    p = fmaf(p, f, 6.93147182e-1f);
    p = fmaf(p, f, 1.0f);
    return __int_as_float((n + 127) << 23) * p;
}

// fp32 pair -> fp16 hi/lo pair at half2-element index o (lo optional)
__device__ __forceinline__ void store_hl_h2(
    void* Ohi, void* Olo, size_t o, float x0, float x1)
{
    __half2 hh = __floats2half2_rn(x0, x1);
    ((__half2*)Ohi)[o] = hh;
    if (Olo) {
        float l0 = x0 - __half2float(__low2half(hh));
        float l1 = x1 - __half2float(__high2half(hh));
        ((__half2*)Olo)[o] = __floats2half2_rn(l0, l1);
    }
}

// ================= generic split tensor-core GEMM ========================
// MODE 0: bf16 3-term  (A = bf16 hi/lo gmem)         C = Ah·Bh + Ah·Bl + Al·Bh
// MODE 1: fp16 2-term  (A = fp16 gmem)               C = A·Bh + A·Bl
// MODE 2: fp16 2-term  (A = fp32 e-values; reg-prefetched; p = e*rinv[row]
//                       written back to C and fed to MMA as fp16)
// B: [N,K] 16-bit hi/lo row-major.  Tiles 128 x BN, BK=32, 2-stage cp.async.
// EPI 0: fp32 C (+bias, alpha, batch strides)
// EPI 1: fp16 hi/lo head-major [bh][s][d] (+bias); Olo optional
// EPI 2: fp16 row-major [token][E] at col (z%zdiv)*64 + col
// EPI 3: scores: write e=exp(alpha*acc) to C + per-(row,colblock) sums to gps
template<int BN, int MODE, int EPI>
__global__ __launch_bounds__(256) void hilo_gemm(
    const void* __restrict__ Ahi_, const void* __restrict__ Alo_,
    const void* __restrict__ Bhi_, const void* __restrict__ Blo_,
    const float* __restrict__ bias, float* __restrict__ C,
    void* __restrict__ Ohi, void* __restrict__ Olo,
    const float* __restrict__ rinv, float* __restrict__ gps,
    int K, int ldA, int ldB, int ldC,
    long long strideA, long long strideB,
    long long sCo, long long sCi, int zdiv, float alpha)
{
    constexpr int NI     = BN / 16;
    constexpr int SSA    = 128 * 80;
    constexpr int ATILES = (MODE == 0) ? 2 : 1;
    constexpr int BOF    = BN * 80;
    constexpr int SS     = ATILES * SSA + 2 * BOF;
    extern __shared__ __align__(16) char smem[];
    const uint32_t sbase = smem_u32(smem);
    __shared__ float s_r[128];

    const int tid  = threadIdx.x;
    const int lane = tid & 31;
    const int wid  = tid >> 5;
    const int m0w  = (wid >> 1) * 32;
    const int n0w  = (wid & 1) * (BN / 2);
    const int m0   = blockIdx.y * 128;
    const int n0   = blockIdx.x * BN;
    const size_t z = blockIdx.z;

    const uint16_t* Ah16 = nullptr;
    const uint16_t* Al16 = nullptr;
    const float*    Af   = nullptr;
    float*          AfW  = nullptr;
    if (MODE == 2) {
        Af  = (const float*)Ahi_ + z * strideA + (size_t)m0 * ldA;
        AfW = C + z * strideA + (size_t)m0 * ldA;
        if (tid < 128) s_r[tid] = rinv[z * S_ + m0 + tid];
        __syncthreads();
    } else {
        Ah16 = (const uint16_t*)Ahi_ + z * strideA + (size_t)m0 * ldA;
        if (MODE == 0)
            Al16 = (const uint16_t*)Alo_ + z * strideA + (size_t)m0 * ldA;
    }
    const uint16_t* Bh = (const uint16_t*)Bhi_ + z * strideB + (size_t)n0 * ldB;
    const uint16_t* Bl = (const uint16_t*)Blo_ + z * strideB + (size_t)n0 * ldB;

    const int T = K / 32;
    float acc[2][NI][4];
    #pragma unroll
    for (int i = 0; i < 2; i++)
        #pragma unroll
        for (int j = 0; j < NI; j++)
            #pragma unroll
            for (int q = 0; q < 4; q++) acc[i][j][q] = 0.0f;

    auto load_B = [&](int it) {
        const uint32_t sb = sbase + (it & 1) * SS;
        const int k0 = it * 32;
        #pragma unroll
        for (int c = tid; c < BN * 8; c += 256) {
            int tile = (c >= BN * 4) ? 1 : 0;
            int cc   = c - tile * BN * 4;
            int r    = cc >> 2, seg = cc & 3;
            const uint16_t* src = (tile ? Bl : Bh) + (size_t)r * ldB + k0 + seg * 8;
            cp16(sb + ATILES * SSA + tile * BOF + r * 80 + seg * 16, src);
        }
    };
    auto load_A_async = [&](int it) {   // MODE 0 / 1 only
        const uint32_t sb = sbase + (it & 1) * SS;
        const int k0 = it * 32;
        if (MODE == 0) {
            #pragma unroll
            for (int c = tid; c < 1024; c += 256) {
                int tile = c >> 9;
                int r = (c >> 2) & 127, seg = c & 3;
                const uint16_t* src = (tile ? Al16 : Ah16) + (size_t)r * ldA + k0 + seg * 8;
                cp16(sb + tile * SSA + r * 80 + seg * 16, src);
            }
        } else if (MODE == 1) {
            #pragma unroll
            for (int c = tid; c < 512; c += 256) {
                int r = c >> 2, seg = c & 3;
                cp16(sb + r * 80 + seg * 16, Ah16 + (size_t)r * ldA + k0 + seg * 8);
            }
        }
    };
    // MODE 2: issue A-tile loads into registers (no use -> latency hideable)
    auto ldg_A = [&](int it, float4* regs) {
        const int k0 = it * 32;
        #pragma unroll
        for (int l = 0; l < 4; l++) {
            int c = tid + l * 256;
            int r = c >> 3, seg = c & 7;
            regs[l] = *(const float4*)(Af + (size_t)r * ldA + k0 + seg * 4);
        }
    };
    // MODE 2: p = e*rinv, write weights, convert to fp16 into smem
    auto sts_A = [&](int it, const float4* regs) {
        char* sp = smem + (it & 1) * SS;
        const int k0 = it * 32;
        #pragma unroll
        for (int l = 0; l < 4; l++) {
            int c = tid + l * 256;
            int r = c >> 3, seg = c & 7;
            float4 v = regs[l];
            const float rv = s_r[r];
            v.x *= rv; v.y *= rv; v.z *= rv; v.w *= rv;
            *(float4*)(AfW + (size_t)r * ldA + k0 + seg * 4) = v;
            __half2 h01 = __floats2half2_rn(v.x, v.y);
            __half2 h23 = __floats2half2_rn(v.z, v.w);
            *(uint32_t*)(sp + r * 80 + seg * 8)     = *(uint32_t*)&h01;
            *(uint32_t*)(sp + r * 80 + seg * 8 + 4) = *(uint32_t*)&h23;
        }
    };

    auto do_mmas = [&](int it) {
        const uint32_t sA = sbase + (it & 1) * SS;
        const uint32_t sB = sA + ATILES * SSA;
        #pragma unroll
        for (int kk = 0; kk < 2; kk++) {
            uint32_t ah[2][4], al[2][4];
            #pragma unroll
            for (int mi = 0; mi < 2; mi++) {
                uint32_t addr = sA + ((m0w + mi * 16 + (lane & 15)) * 40
                                      + kk * 16 + ((lane >> 4) << 3)) * 2;
                LDSM4(ah[mi], addr);
                if (MODE == 0) LDSM4(al[mi], addr + SSA);
            }
            uint32_t bh[NI][2], bl[NI][2];
            #pragma unroll
            for (int nj = 0; nj < NI / 2; nj++) {
                uint32_t row = n0w + nj * 16 + (lane & 7) + ((lane >> 4) << 3);
                uint32_t col = kk * 16 + (((lane >> 3) & 1) << 3);
                uint32_t addr = sB + (row * 40 + col) * 2;
                uint32_t t4[4];
                LDSM4(t4, addr);
                bh[2 * nj][0] = t4[0]; bh[2 * nj][1] = t4[1];
                bh[2 * nj + 1][0] = t4[2]; bh[2 * nj + 1][1] = t4[3];
                LDSM4(t4, addr + BOF);
                bl[2 * nj][0] = t4[0]; bl[2 * nj][1] = t4[1];
                bl[2 * nj + 1][0] = t4[2]; bl[2 * nj + 1][1] = t4[3];
            }
            #pragma unroll
            for (int mi = 0; mi < 2; mi++)
                #pragma unroll
                for (int ni = 0; ni < NI; ni++) {
                    if (MODE == 0) {
                        MMA_BF16(acc[mi][ni], ah[mi], bh[ni][0], bh[ni][1]);
                        MMA_BF16(acc[mi][ni], ah[mi], bl[ni][0], bl[ni][1]);
                        MMA_BF16(acc[mi][ni], al[mi], bh[ni][0], bh[ni][1]);
                    } else {
                        MMA_F16(acc[mi][ni], ah[mi], bh[ni][0], bh[ni][1]);
                        MMA_F16(acc[mi][ni], ah[mi], bl[ni][0], bl[ni][1]);
                    }
                }
        }
    };

    if (MODE == 2) {
        // register-prefetched A pipeline: LDG issues hide under MMAs
        float4 regs[4];
        ldg_A(0, regs);
        load_B(0);
        asm volatile("cp.async.commit_group;" ::: "memory");
        sts_A(0, regs);
        float4 regsN[4];
        for (int it = 0; it < T; it++) {
            if (it + 1 < T) {
                ldg_A(it + 1, regsN);          // issue early, consumed post-MMA
                load_B(it + 1);
                asm volatile("cp.async.commit_group;" ::: "memory");
                asm volatile("cp.async.wait_group 1;" ::: "memory");
            } else {
                asm volatile("cp.async.wait_group 0;" ::: "memory");
            }
            __syncthreads();
            do_mmas(it);
            __syncthreads();
            if (it + 1 < T) sts_A(it + 1, regsN);
        }
    } else {
        load_A_async(0);
        load_B(0);
        asm volatile("cp.async.commit_group;" ::: "memory");
        for (int it = 0; it < T; it++) {
            if (it + 1 < T) {
                load_A_async(it + 1);
                load_B(it + 1);
                asm volatile("cp.async.commit_group;" ::: "memory");
                asm volatile("cp.async.wait_group 1;" ::: "memory");
            } else {
                asm volatile("cp.async.wait_group 0;" ::: "memory");
            }
            __syncthreads();
            do_mmas(it);
            __syncthreads();
        }
    }

    // ---------------- epilogue ----------------
    if (EPI == 0) {
        float* Cz = C + (z / zdiv) * sCo + (z % zdiv) * sCi;
        #pragma unroll
        for (int mi = 0; mi < 2; mi++)
            #pragma unroll
            for (int ni = 0; ni < NI; ni++) {
                int row = m0 + m0w + mi * 16 + (lane >> 2);
                int col = n0 + n0w + ni * 8 + ((lane & 3) << 1);
                float b0 = bias ? __ldg(bias + col) : 0.0f;
                float b1 = bias ? __ldg(bias + col + 1) : 0.0f;
                Cz[(size_t)row * ldC + col]           = acc[mi][ni][0] * alpha + b0;
                Cz[(size_t)row * ldC + col + 1]       = acc[mi][ni][1] * alpha + b1;
                Cz[(size_t)(row + 8) * ldC + col]     = acc[mi][ni][2] * alpha + b0;
                Cz[(size_t)(row + 8) * ldC + col + 1] = acc[mi][ni][3] * alpha + b1;
            }
    } else if (EPI == 1) {
        #pragma unroll
        for (int mi = 0; mi < 2; mi++)
            #pragma unroll
            for (int ni = 0; ni < NI; ni++) {
                int row = m0 + m0w + mi * 16 + (lane >> 2);
                int col = n0 + n0w + ni * 8 + ((lane & 3) << 1);
                float b0 = bias ? __ldg(bias + col) : 0.0f;
                float b1 = bias ? __ldg(bias + col + 1) : 0.0f;
                int h = col >> 6, d = col & 63;
                #pragma unroll
                for (int rr = 0; rr < 2; rr++) {
                    int r = row + rr * 8;
                    int b = r >> 11, s = r & 2047;
                    size_t o = ((((size_t)(b * 16 + h)) * S_ + s) * D_ + d) >> 1;
                    store_hl_h2(Ohi, Olo, o,
                                acc[mi][ni][rr * 2 + 0] + b0,
                                acc[mi][ni][rr * 2 + 1] + b1);
                }
            }
    } else if (EPI == 2) {
        const int b = (int)z / zdiv, h = (int)z % zdiv;
        #pragma unroll
        for (int mi = 0; mi < 2; mi++)
            #pragma unroll
            for (int ni = 0; ni < NI; ni++) {
                int srow = m0 + m0w + mi * 16 + (lane >> 2);
                int col  = n0 + n0w + ni * 8 + ((lane & 3) << 1);
                #pragma unroll
                for (int rr = 0; rr < 2; rr++) {
                    int s = srow + rr * 8;
                    size_t token = (size_t)b * S_ + s;
                    size_t o = (token * E_ + h * D_ + col) >> 1;
                    ((__half2*)Ohi)[o] =
                        __floats2half2_rn(acc[mi][ni][rr * 2 + 0],
                                          acc[mi][ni][rr * 2 + 1]);
                }
            }
    } else {
        // EPI == 3: scores — write e = exp(alpha*acc), accumulate row sums
        __shared__ float ps_s[128][2];
        float* Cz = C + z * sCo;
        float rs[2][2] = {{0.0f, 0.0f}, {0.0f, 0.0f}};
        #pragma unroll
        for (int mi = 0; mi < 2; mi++)
            #pragma unroll
            for (int ni = 0; ni < NI; ni++) {
                int row = m0 + m0w + mi * 16 + (lane >> 2);
                int col = n0 + n0w + ni * 8 + ((lane & 3) << 1);
                float e0 = fast_exp(acc[mi][ni][0] * alpha);
                float e1 = fast_exp(acc[mi][ni][1] * alpha);
                float e2 = fast_exp(acc[mi][ni][2] * alpha);
                float e3 = fast_exp(acc[mi][ni][3] * alpha);
                Cz[(size_t)row * ldC + col]           = e0;
                Cz[(size_t)row * ldC + col + 1]       = e1;
                Cz[(size_t)(row + 8) * ldC + col]     = e2;
                Cz[(size_t)(row + 8) * ldC + col + 1] = e3;
                rs[mi][0] += e0 + e1;
                rs[mi][1] += e2 + e3;
            }
        #pragma unroll
        for (int mi = 0; mi < 2; mi++)
            #pragma unroll
            for (int rr = 0; rr < 2; rr++) {
                float v = rs[mi][rr];
                v += __shfl_xor_sync(0xFFFFFFFFu, v, 1);
                v += __shfl_xor_sync(0xFFFFFFFFu, v, 2);
                rs[mi][rr] = v;
            }
        if ((lane & 3) == 0) {
            #pragma unroll
            for (int mi = 0; mi < 2; mi++)
                #pragma unroll
                for (int rr = 0; rr < 2; rr++)
                    ps_s[m0w + mi * 16 + (lane >> 2) + rr * 8][wid & 1] = rs[mi][rr];
        }
        __syncthreads();
        if (tid < 128) {
            size_t o = ((size_t)z * gridDim.x + blockIdx.x) * (size_t)S_ + m0 + tid;
            gps[o] = ps_s[tid][0] + ps_s[tid][1];
        }
    }
}

// ---------------- combine: rinv = 1 / sum of 16 col-block partials -------
__global__ __launch_bounds__(256) void combine_kernel(
    const float* __restrict__ gps, float* __restrict__ rinv)
{
    int g = blockIdx.x * 256 + threadIdx.x;        // [BH*2048)
    int bh = g >> 11, r = g & 2047;
    const float* ps = gps + (size_t)bh * 16 * S_ + r;
    float s = 0.0f;
    #pragma unroll
    for (int jb = 0; jb < 16; jb++) s += ps[(size_t)jb * S_];
    rinv[g] = 1.0f / s;
}

// ================= conversions ===========================================
__global__ __launch_bounds__(256) void conv_hilo4_kernel(
    const float4* __restrict__ in, __nv_bfloat162* __restrict__ hi,
    __nv_bfloat162* __restrict__ lo, int n4)
{
    int i = blockIdx.x * 256 + threadIdx.x;
    if (i < n4) {
        float4 v = in[i];
        __nv_bfloat162 h01 = __floats2bfloat162_rn(v.x, v.y);
        __nv_bfloat162 h23 = __floats2bfloat162_rn(v.z, v.w);
        hi[2 * i]     = h01;
        hi[2 * i + 1] = h23;
        lo[2 * i]     = __floats2bfloat162_rn(v.x - __bfloat162float(h01.x),
                                              v.y - __bfloat162float(h01.y));
        lo[2 * i + 1] = __floats2bfloat162_rn(v.z - __bfloat162float(h23.x),
                                              v.w - __bfloat162float(h23.y));
    }
}

// W[K,N] fp32 -> Wt[N,K] bf16 hi/lo
__global__ __launch_bounds__(256) void transconv_bf_kernel(
    const float* __restrict__ W, __nv_bfloat16* __restrict__ hi,
    __nv_bfloat16* __restrict__ lo, int K, int N)
{
    __shared__ float t[32][33];
    const int k0 = blockIdx.y * 32, n0 = blockIdx.x * 32;
    const int tx = threadIdx.x & 31, ty = threadIdx.x >> 5;
    #pragma unroll
    for (int i = 0; i < 32; i += 8)
        t[ty + i][tx] = W[(size_t)(k0 + ty + i) * N + n0 + tx];
    __syncthreads();
    #pragma unroll
    for (int i = 0; i < 32; i += 8) {
        float x = t[tx][ty + i];
        __nv_bfloat16 h = __float2bfloat16(x);
        size_t o = (size_t)(n0 + ty + i) * K + k0 + tx;
        hi[o] = h;
        lo[o] = __float2bfloat16(x - __bfloat162float(h));
    }
}

// W[K,N] fp32 -> Wt[N,K] fp16 hi/lo
__global__ __launch_bounds__(256) void transconv_h_kernel(
    const float* __restrict__ W, __half* __restrict__ hi,
    __half* __restrict__ lo, int K, int N)
{
    __shared__ float t[32][33];
    const int k0 = blockIdx.y * 32, n0 = blockIdx.x * 32;
    const int tx = threadIdx.x & 31, ty = threadIdx.x >> 5;
    #pragma unroll
    for (int i = 0; i < 32; i += 8)
        t[ty + i][tx] = W[(size_t)(k0 + ty + i) * N + n0 + tx];
    __syncthreads();
    #pragma unroll
    for (int i = 0; i < 32; i += 8) {
        float x = t[tx][ty + i];
        __half h = __float2half_rn(x);
        size_t o = (size_t)(n0 + ty + i) * K + k0 + tx;
        hi[o] = h;
        lo[o] = __float2half_rn(x - __half2float(h));
    }
}

// [bh][s][d] 16-bit -> [bh][d][s] 16-bit (hi and lo together)
__global__ __launch_bounds__(256) void transpose16_kernel(
    const uint16_t* __restrict__ hi_in, const uint16_t* __restrict__ lo_in,
    uint16_t* __restrict__ hi_out, uint16_t* __restrict__ lo_out)
{
    __shared__ uint16_t th[32][33];
    __shared__ uint16_t tl[32][33];
    const int bh = blockIdx.z;
    const int s0 = blockIdx.x * 32, d0 = blockIdx.y * 32;
    const int tx = threadIdx.x & 31, ty = threadIdx.x >> 5;
    #pragma unroll
    for (int i = 0; i < 32; i += 8) {
        size_t src = ((size_t)bh * S_ + s0 + ty + i) * D_ + d0 + tx;
        th[ty + i][tx] = hi_in[src];
        tl[ty + i][tx] = lo_in[src];
    }
    __syncthreads();
    #pragma unroll
    for (int i = 0; i < 32; i += 8) {
        size_t dst = ((size_t)bh * D_ + d0 + ty + i) * S_ + s0 + tx;
        hi_out[dst] = th[tx][ty + i];
        lo_out[dst] = tl[tx][ty + i];
    }
}

// ---------------- launch ----------------
extern "C" void kernel_launch(void* const* d_in, const int* in_sizes, int n_in,
                              void* d_out, int out_size)
{
    const float* query = (const float*)d_in[0];
    const float* key   = (const float*)d_in[1];
    const float* value = (const float*)d_in[2];
    const float* Wq    = (const float*)d_in[3];
    const float* bq    = (const float*)d_in[4];
    const float* Wk    = (const float*)d_in[5];
    const float* bk    = (const float*)d_in[6];
    const float* Wv    = (const float*)d_in[7];
    const float* bv    = (const float*)d_in[8];
    const float* Wo    = (const float*)d_in[9];
    const float* bo    = (const float*)d_in[10];

    float* out  = (float*)d_out;                 // [B,S,E]
    float* Wbuf = out + (size_t)M_ * E_;         // [B,H,S,S]

    __nv_bfloat16 *ahi, *alo, *whi, *wlo;
    __half *wohi, *wolo, *qhi, *khi, *klo, *vhi, *vlo, *vthi, *vtlo, *ctxh;
    float *gps, *gri;
    cudaGetSymbolAddress((void**)&ahi,  g_Ahi);
    cudaGetSymbolAddress((void**)&alo,  g_Alo);
    cudaGetSymbolAddress((void**)&whi,  g_Whi);
    cudaGetSymbolAddress((void**)&wlo,  g_Wlo);
    cudaGetSymbolAddress((void**)&wohi, g_Wohi);
    cudaGetSymbolAddress((void**)&wolo, g_Wolo);
    cudaGetSymbolAddress((void**)&qhi,  g_qhi);
    cudaGetSymbolAddress((void**)&khi,  g_khi);
    cudaGetSymbolAddress((void**)&klo,  g_klo);
    cudaGetSymbolAddress((void**)&vhi,  g_vhi);
    cudaGetSymbolAddress((void**)&vlo,  g_vlo);
    cudaGetSymbolAddress((void**)&vthi, g_vthi);
    cudaGetSymbolAddress((void**)&vtlo, g_vtlo);
    cudaGetSymbolAddress((void**)&ctxh, g_ctxh);
    cudaGetSymbolAddress((void**)&gps,  g_psum);
    cudaGetSymbolAddress((void**)&gri,  g_rinv);

    const int SMEM_PROJ = 2 * (2 * 128 * 80 + 2 * 128 * 80);  // 81920
    const int SMEM_H16  = 2 * (1 * 128 * 80 + 2 * 128 * 80);  // 61440
    const int SMEM_AV   = 2 * (1 * 128 * 80 + 2 * 64 * 80);   // 40960
    cudaFuncSetAttribute(hilo_gemm<128, 0, 1>,
                         cudaFuncAttributeMaxDynamicSharedMemorySize, SMEM_PROJ);
    cudaFuncSetAttribute(hilo_gemm<128, 1, 3>,
                         cudaFuncAttributeMaxDynamicSharedMemorySize, SMEM_H16);
    cudaFuncSetAttribute(hilo_gemm<128, 1, 0>,
                         cudaFuncAttributeMaxDynamicSharedMemorySize, SMEM_H16);
    cudaFuncSetAttribute(hilo_gemm<64, 2, 2>,
                         cudaFuncAttributeMaxDynamicSharedMemorySize, SMEM_AV);

    // ---- projections (bf16 3-term, write head-major fp16 hi/lo) ----
    conv_hilo4_kernel<<<(M_ * QD_ / 4 + 255) / 256, 256>>>(
        (const float4*)query, (__nv_bfloat162*)ahi, (__nv_bfloat162*)alo, M_ * QD_ / 4);
    transconv_bf_kernel<<<dim3(E_ / 32, QD_ / 32), 256>>>(Wq, whi, wlo, QD_, E_);
    hilo_gemm<128, 0, 1><<<dim3(E_ / 128, M_ / 128, 1), 256, SMEM_PROJ>>>(
        ahi, alo, whi, wlo, bq, nullptr, qhi, nullptr, nullptr, nullptr,
        QD_, QD_, QD_, E_, 0, 0, 0, 0, 1, 1.0f);

    conv_hilo4_kernel<<<(M_ * KD_ / 4 + 255) / 256, 256>>>(
        (const float4*)key, (__nv_bfloat162*)ahi, (__nv_bfloat162*)alo, M_ * KD_ / 4);
    transconv_bf_kernel<<<dim3(E_ / 32, KD_ / 32), 256>>>(Wk, whi, wlo, KD_, E_);
    hilo_gemm<128, 0, 1><<<dim3(E_ / 128, M_ / 128, 1), 256, SMEM_PROJ>>>(
        ahi, alo, whi, wlo, bk, nullptr, khi, klo, nullptr, nullptr,
        KD_, KD_, KD_, E_, 0, 0, 0, 0, 1, 1.0f);

    conv_hilo4_kernel<<<(M_ * VD_ / 4 + 255) / 256, 256>>>(
        (const float4*)value, (__nv_bfloat162*)ahi, (__nv_bfloat162*)alo, M_ * VD_ / 4);
    transconv_bf_kernel<<<dim3(E_ / 32, VD_ / 32), 256>>>(Wv, whi, wlo, VD_, E_);
    hilo_gemm<128, 0, 1><<<dim3(E_ / 128, M_ / 128, 1), 256, SMEM_PROJ>>>(
        ahi, alo, whi, wlo, bv, nullptr, vhi, vlo, nullptr, nullptr,
        VD_, VD_, VD_, E_, 0, 0, 0, 0, 1, 1.0f);

    transpose16_kernel<<<dim3(S_ / 32, D_ / 32, BH_), 256>>>(
        (const uint16_t*)vhi, (const uint16_t*)vlo,
        (uint16_t*)vthi, (uint16_t*)vtlo);

    // ---- scores: fp16 2-term, Wbuf = exp(0.125 * q.k), row-sum partials ----
    hilo_gemm<128, 1, 3><<<dim3(S_ / 128, S_ / 128, BH_), 256, SMEM_H16>>>(
        qhi, nullptr, khi, klo, nullptr, Wbuf, nullptr, nullptr, nullptr, gps,
        D_, D_, D_, S_,
        (long long)S_ * D_, (long long)S_ * D_,
        (long long)S_ * S_, 0, 1, 0.125f);

    // ---- combine partial sums -> rinv ----
    combine_kernel<<<(BH_ * S_) / 256, 256>>>(gps, gri);

    // ---- AV: reg-prefetched p = e*rinv (weights written), ctx fp16 out ----
    hilo_gemm<64, 2, 2><<<dim3(1, S_ / 128, BH_), 256, SMEM_AV>>>(
        Wbuf, nullptr, vthi, vtlo, nullptr, Wbuf, ctxh, nullptr, gri, nullptr,
        S_, S_, S_, E_,
        (long long)S_ * S_, (long long)D_ * S_,
        0, 0, 16, 1.0f);

    // ---- output projection: fp16 2-term (A = ctx fp16) ----
    transconv_h_kernel<<<dim3(E_ / 32, E_ / 32), 256>>>(Wo, wohi, wolo, E_, E_);
    hilo_gemm<128, 1, 0><<<dim3(E_ / 128, M_ / 128, 1), 256, SMEM_H16>>>(
        ctxh, nullptr, wohi, wolo, bo, out, nullptr, nullptr, nullptr, nullptr,
        E_, E_, E_, E_, 0, 0, 0, 0, 1, 1.0f);
}

// round 13
// speedup vs baseline: 1.1151x; 1.0287x over previous
#include <cuda_runtime.h>
#include <cuda_bf16.h>
#include <cuda_fp16.h>
#include <cstdint>

#define B_   4
#define S_   2048
#define E_   1024
#define H_   16
#define D_   64
#define QD_  1024
#define KD_  768
#define VD_  768
#define M_   (B_ * S_)          // 8192
#define BH_  (B_ * H_)          // 64

// ---------------- device scratch (no allocations allowed) ----------------
__device__ __align__(16) __nv_bfloat16 g_Ahi[M_ * E_];
__device__ __align__(16) __nv_bfloat16 g_Alo[M_ * E_];
__device__ __align__(16) __nv_bfloat16 g_Whi[E_ * E_];
__device__ __align__(16) __nv_bfloat16 g_Wlo[E_ * E_];
__device__ __align__(16) __half g_Wohi[E_ * E_];
__device__ __align__(16) __half g_Wolo[E_ * E_];
__device__ __align__(16) __half g_qhi[BH_ * S_ * D_];
__device__ __align__(16) __half g_khi[BH_ * S_ * D_];
__device__ __align__(16) __half g_klo[BH_ * S_ * D_];
__device__ __align__(16) __half g_vhi[BH_ * S_ * D_];
__device__ __align__(16) __half g_vlo[BH_ * S_ * D_];
__device__ __align__(16) __half g_vthi[BH_ * D_ * S_];
__device__ __align__(16) __half g_vtlo[BH_ * D_ * S_];
__device__ __align__(16) __half g_ctxh[M_ * E_];
__device__ float g_psum[BH_ * 16 * S_];
__device__ float g_rinv[BH_ * S_];

// ======================= helpers ============================
__device__ __forceinline__ uint32_t smem_u32(const void* p) {
    uint32_t a;
    asm("{ .reg .u64 t; cvta.to.shared.u64 t, %1; cvt.u32.u64 %0, t; }"
        : "=r"(a) : "l"(p));
    return a;
}
__device__ __forceinline__ void cp16(uint32_t dst, const void* src) {
    asm volatile("cp.async.cg.shared.global [%0], [%1], 16;" :: "r"(dst), "l"(src));
}
#define LDSM4(R, addr) \
    asm volatile("ldmatrix.sync.aligned.m8n8.x4.shared.b16 {%0,%1,%2,%3}, [%4];" \
                 : "=r"((R)[0]), "=r"((R)[1]), "=r"((R)[2]), "=r"((R)[3]) : "r"(addr))
#define MMA_BF16(c, a, b0, b1) \
    asm volatile("mma.sync.aligned.m16n8k16.row.col.f32.bf16.bf16.f32 " \
                 "{%0,%1,%2,%3}, {%4,%5,%6,%7}, {%8,%9}, {%0,%1,%2,%3};" \
                 : "+f"((c)[0]), "+f"((c)[1]), "+f"((c)[2]), "+f"((c)[3]) \
                 : "r"((a)[0]), "r"((a)[1]), "r"((a)[2]), "r"((a)[3]), "r"(b0), "r"(b1))
#define MMA_F16(c, a, b0, b1) \
    asm volatile("mma.sync.aligned.m16n8k16.row.col.f32.f16.f16.f32 " \
                 "{%0,%1,%2,%3}, {%4,%5,%6,%7}, {%8,%9}, {%0,%1,%2,%3};" \
                 : "+f"((c)[0]), "+f"((c)[1]), "+f"((c)[2]), "+f"((c)[3]) \
                 : "r"((a)[0]), "r"((a)[1]), "r"((a)[2]), "r"((a)[3]), "r"(b0), "r"(b1))

__device__ __forceinline__ float fast_exp(float x) {
    float t = x * 1.44269504088896341f;
    t = fmaxf(t, -125.0f);
    float r = t + 12582912.0f;
    int   n = __float_as_int(r) - 0x4B400000;
    float f = t - (r - 12582912.0f);
    float p = 1.33336498e-3f;
    p = fmaf(p, f, 9.61011466e-3f);
    p = fmaf(p, f, 5.55036595e-2f);
    p = fmaf(p, f, 2.40226510e-1f);
    p = fmaf(p, f, 6.93147182e-1f);
    p = fmaf(p, f, 1.0f);
    return __int_as_float((n + 127) << 23) * p;
}

// fp32 pair -> fp16 hi/lo pair at half2-element index o (lo optional)
__device__ __forceinline__ void store_hl_h2(
    void* Ohi, void* Olo, size_t o, float x0, float x1)
{
    __half2 hh = __floats2half2_rn(x0, x1);
    ((__half2*)Ohi)[o] = hh;
    if (Olo) {
        float l0 = x0 - __half2float(__low2half(hh));
        float l1 = x1 - __half2float(__high2half(hh));
        ((__half2*)Olo)[o] = __floats2half2_rn(l0, l1);
    }
}

// ================= generic split tensor-core GEMM ========================
// MODE 0: bf16 3-term  (A = bf16 hi/lo gmem)         C = Ah·Bh + Ah·Bl + Al·Bh
// MODE 1: fp16 2-term  (A = fp16 gmem)               C = A·Bh + A·Bl
// EPI 0: fp32 C (+bias, alpha, batch strides)
// EPI 1: fp16 hi/lo head-major [bh][s][d] (+bias); Olo optional
// EPI 4: stats only — per-(row,colblock) sums of exp(alpha*acc) to gps, no C
template<int BN, int MODE, int EPI>
__global__ __launch_bounds__(256) void hilo_gemm(
    const void* __restrict__ Ahi_, const void* __restrict__ Alo_,
    const void* __restrict__ Bhi_, const void* __restrict__ Blo_,
    const float* __restrict__ bias, float* __restrict__ C,
    void* __restrict__ Ohi, void* __restrict__ Olo,
    float* __restrict__ gps,
    int K, int ldA, int ldB, int ldC,
    long long strideA, long long strideB,
    long long sCo, long long sCi, int zdiv, float alpha)
{
    constexpr int NI     = BN / 16;
    constexpr int SSA    = 128 * 80;
    constexpr int ATILES = (MODE == 0) ? 2 : 1;
    constexpr int BOF    = BN * 80;
    constexpr int SS     = ATILES * SSA + 2 * BOF;
    extern __shared__ __align__(16) char smem[];
    const uint32_t sbase = smem_u32(smem);

    const int tid  = threadIdx.x;
    const int lane = tid & 31;
    const int wid  = tid >> 5;
    const int m0w  = (wid >> 1) * 32;
    const int n0w  = (wid & 1) * (BN / 2);
    const int m0   = blockIdx.y * 128;
    const int n0   = blockIdx.x * BN;
    const size_t z = blockIdx.z;

    const uint16_t* Ah16 = (const uint16_t*)Ahi_ + z * strideA + (size_t)m0 * ldA;
    const uint16_t* Al16 = nullptr;
    if (MODE == 0)
        Al16 = (const uint16_t*)Alo_ + z * strideA + (size_t)m0 * ldA;
    const uint16_t* Bh = (const uint16_t*)Bhi_ + z * strideB + (size_t)n0 * ldB;
    const uint16_t* Bl = (const uint16_t*)Blo_ + z * strideB + (size_t)n0 * ldB;

    const int T = K / 32;
    float acc[2][NI][4];
    #pragma unroll
    for (int i = 0; i < 2; i++)
        #pragma unroll
        for (int j = 0; j < NI; j++)
            #pragma unroll
            for (int q = 0; q < 4; q++) acc[i][j][q] = 0.0f;

    auto load_stage = [&](int it) {
        const uint32_t sb = sbase + (it & 1) * SS;
        const int k0 = it * 32;
        #pragma unroll
        for (int c = tid; c < BN * 8; c += 256) {
            int tile = (c >= BN * 4) ? 1 : 0;
            int cc   = c - tile * BN * 4;
            int r    = cc >> 2, seg = cc & 3;
            const uint16_t* src = (tile ? Bl : Bh) + (size_t)r * ldB + k0 + seg * 8;
            cp16(sb + ATILES * SSA + tile * BOF + r * 80 + seg * 16, src);
        }
        if (MODE == 0) {
            #pragma unroll
            for (int c = tid; c < 1024; c += 256) {
                int tile = c >> 9;
                int r = (c >> 2) & 127, seg = c & 3;
                const uint16_t* src = (tile ? Al16 : Ah16) + (size_t)r * ldA + k0 + seg * 8;
                cp16(sb + tile * SSA + r * 80 + seg * 16, src);
            }
        } else {
            #pragma unroll
            for (int c = tid; c < 512; c += 256) {
                int r = c >> 2, seg = c & 3;
                cp16(sb + r * 80 + seg * 16, Ah16 + (size_t)r * ldA + k0 + seg * 8);
            }
        }
    };

    auto do_mmas = [&](int it) {
        const uint32_t sA = sbase + (it & 1) * SS;
        const uint32_t sB = sA + ATILES * SSA;
        #pragma unroll
        for (int kk = 0; kk < 2; kk++) {
            uint32_t ah[2][4], al[2][4];
            #pragma unroll
            for (int mi = 0; mi < 2; mi++) {
                uint32_t addr = sA + ((m0w + mi * 16 + (lane & 15)) * 40
                                      + kk * 16 + ((lane >> 4) << 3)) * 2;
                LDSM4(ah[mi], addr);
                if (MODE == 0) LDSM4(al[mi], addr + SSA);
            }
            uint32_t bh[NI][2], bl[NI][2];
            #pragma unroll
            for (int nj = 0; nj < NI / 2; nj++) {
                uint32_t row = n0w + nj * 16 + (lane & 7) + ((lane >> 4) << 3);
                uint32_t col = kk * 16 + (((lane >> 3) & 1) << 3);
                uint32_t addr = sB + (row * 40 + col) * 2;
                uint32_t t4[4];
                LDSM4(t4, addr);
                bh[2 * nj][0] = t4[0]; bh[2 * nj][1] = t4[1];
                bh[2 * nj + 1][0] = t4[2]; bh[2 * nj + 1][1] = t4[3];
                LDSM4(t4, addr + BOF);
                bl[2 * nj][0] = t4[0]; bl[2 * nj][1] = t4[1];
                bl[2 * nj + 1][0] = t4[2]; bl[2 * nj + 1][1] = t4[3];
            }
            #pragma unroll
            for (int mi = 0; mi < 2; mi++)
                #pragma unroll
                for (int ni = 0; ni < NI; ni++) {
                    if (MODE == 0) {
                        MMA_BF16(acc[mi][ni], ah[mi], bh[ni][0], bh[ni][1]);
                        MMA_BF16(acc[mi][ni], ah[mi], bl[ni][0], bl[ni][1]);
                        MMA_BF16(acc[mi][ni], al[mi], bh[ni][0], bh[ni][1]);
                    } else {
                        MMA_F16(acc[mi][ni], ah[mi], bh[ni][0], bh[ni][1]);
                        MMA_F16(acc[mi][ni], ah[mi], bl[ni][0], bl[ni][1]);
                    }
                }
        }
    };

    load_stage(0);
    asm volatile("cp.async.commit_group;" ::: "memory");
    for (int it = 0; it < T; it++) {
        if (it + 1 < T) {
            load_stage(it + 1);
            asm volatile("cp.async.commit_group;" ::: "memory");
            asm volatile("cp.async.wait_group 1;" ::: "memory");
        } else {
            asm volatile("cp.async.wait_group 0;" ::: "memory");
        }
        __syncthreads();
        do_mmas(it);
        __syncthreads();
    }

    // ---------------- epilogue ----------------
    if (EPI == 0) {
        float* Cz = C + (z / zdiv) * sCo + (z % zdiv) * sCi;
        #pragma unroll
        for (int mi = 0; mi < 2; mi++)
            #pragma unroll
            for (int ni = 0; ni < NI; ni++) {
                int row = m0 + m0w + mi * 16 + (lane >> 2);
                int col = n0 + n0w + ni * 8 + ((lane & 3) << 1);
                float b0 = bias ? __ldg(bias + col) : 0.0f;
                float b1 = bias ? __ldg(bias + col + 1) : 0.0f;
                Cz[(size_t)row * ldC + col]           = acc[mi][ni][0] * alpha + b0;
                Cz[(size_t)row * ldC + col + 1]       = acc[mi][ni][1] * alpha + b1;
                Cz[(size_t)(row + 8) * ldC + col]     = acc[mi][ni][2] * alpha + b0;
                Cz[(size_t)(row + 8) * ldC + col + 1] = acc[mi][ni][3] * alpha + b1;
            }
    } else if (EPI == 1) {
        #pragma unroll
        for (int mi = 0; mi < 2; mi++)
            #pragma unroll
            for (int ni = 0; ni < NI; ni++) {
                int row = m0 + m0w + mi * 16 + (lane >> 2);
                int col = n0 + n0w + ni * 8 + ((lane & 3) << 1);
                float b0 = bias ? __ldg(bias + col) : 0.0f;
                float b1 = bias ? __ldg(bias + col + 1) : 0.0f;
                int h = col >> 6, d = col & 63;
                #pragma unroll
                for (int rr = 0; rr < 2; rr++) {
                    int r = row + rr * 8;
                    int b = r >> 11, s = r & 2047;
                    size_t o = ((((size_t)(b * 16 + h)) * S_ + s) * D_ + d) >> 1;
                    store_hl_h2(Ohi, Olo, o,
                                acc[mi][ni][rr * 2 + 0] + b0,
                                acc[mi][ni][rr * 2 + 1] + b1);
                }
            }
    } else {
        // EPI == 4: row-sum partials of exp(alpha*acc); no C write
        __shared__ float ps_s[128][2];
        float rs[2][2] = {{0.0f, 0.0f}, {0.0f, 0.0f}};
        #pragma unroll
        for (int mi = 0; mi < 2; mi++)
            #pragma unroll
            for (int ni = 0; ni < NI; ni++) {
                rs[mi][0] += fast_exp(acc[mi][ni][0] * alpha)
                           + fast_exp(acc[mi][ni][1] * alpha);
                rs[mi][1] += fast_exp(acc[mi][ni][2] * alpha)
                           + fast_exp(acc[mi][ni][3] * alpha);
            }
        #pragma unroll
        for (int mi = 0; mi < 2; mi++)
            #pragma unroll
            for (int rr = 0; rr < 2; rr++) {
                float v = rs[mi][rr];
                v += __shfl_xor_sync(0xFFFFFFFFu, v, 1);
                v += __shfl_xor_sync(0xFFFFFFFFu, v, 2);
                rs[mi][rr] = v;
            }
        if ((lane & 3) == 0) {
            #pragma unroll
            for (int mi = 0; mi < 2; mi++)
                #pragma unroll
                for (int rr = 0; rr < 2; rr++)
                    ps_s[m0w + mi * 16 + (lane >> 2) + rr * 8][wid & 1] = rs[mi][rr];
        }
        __syncthreads();
        if (tid < 128) {
            size_t o = ((size_t)z * gridDim.x + blockIdx.x) * (size_t)S_ + m0 + tid;
            gps[o] = ps_s[tid][0] + ps_s[tid][1];
        }
    }
}

// ---------------- combine: rinv = 1 / sum of 16 col-block partials -------
__global__ __launch_bounds__(256) void combine_kernel(
    const float* __restrict__ gps, float* __restrict__ rinv)
{
    int g = blockIdx.x * 256 + threadIdx.x;        // [BH*2048)
    int bh = g >> 11, r = g & 2047;
    const float* ps = gps + (size_t)bh * 16 * S_ + r;
    float s = 0.0f;
    #pragma unroll
    for (int jb = 0; jb < 16; jb++) s += ps[(size_t)jb * S_];
    rinv[g] = 1.0f / s;
}

// ================= flash attention: QK recompute + P write + AV ==========
// Per block: (i-block of 128 q rows, bh).  j-loop over 32 blocks of 64 keys.
// smem: Q[2ch][128][40]h | K[2st][hi/lo][2ch][64][40]h | V same | P[2ch][128][40]h
#define FA_Q0   0
#define FA_K0   20480
#define FA_V0   61440
#define FA_P0   102400
#define FA_SMEM 122880
__global__ __launch_bounds__(256) void flash_av_kernel(
    const __half* __restrict__ qh,
    const __half* __restrict__ khi, const __half* __restrict__ klo,
    const __half* __restrict__ vthi, const __half* __restrict__ vtlo,
    const float* __restrict__ rinv, float* __restrict__ Wbuf,
    __half* __restrict__ ctxh)
{
    extern __shared__ __align__(16) char smem[];
    const uint32_t sbase = smem_u32(smem);
    __shared__ float s_r[128];

    const int tid  = threadIdx.x;
    const int lane = tid & 31;
    const int wid  = tid >> 5;
    const int m0w  = (wid >> 1) * 32;
    const int n0w  = (wid & 1) * 32;
    const int i0   = blockIdx.x * 128;
    const int bh   = blockIdx.y;
    const int bb   = bh >> 4, hh = bh & 15;

    if (tid < 128) s_r[tid] = rinv[(size_t)bh * S_ + i0 + tid];

    // prologue: Q (both chunks) + stage-0 K/V
    const __half* qg = qh + ((size_t)bh * S_ + i0) * D_;
    #pragma unroll
    for (int l = 0; l < 4; l++) {
        int c = tid + l * 256;
        int it = c >> 9, cc = c & 511, r = cc >> 2, seg = cc & 3;
        cp16(sbase + FA_Q0 + it * 10240 + r * 80 + seg * 16,
             qg + (size_t)r * D_ + it * 32 + seg * 8);
    }
    auto load_kv = [&](int j) {
        const int st = j & 1, j0 = j * 64;
        #pragma unroll
        for (int l = 0; l < 4; l++) {
            int c = tid + l * 256;
            int t = c >> 9, cc = c & 511;
            int r = cc >> 3, rem = cc & 7, ch = rem >> 2, seg = rem & 3;
            const __half* src = (t ? klo : khi)
                + ((size_t)bh * S_ + j0 + r) * D_ + ch * 32 + seg * 8;
            cp16(sbase + FA_K0 + st * 20480 + t * 10240 + ch * 5120
                 + r * 80 + seg * 16, src);
        }
        #pragma unroll
        for (int l = 0; l < 4; l++) {
            int c = tid + l * 256;
            int t = c >> 9, cc = c & 511;
            int r = cc >> 3, rem = cc & 7, ch = rem >> 2, seg = rem & 3;
            const __half* src = (t ? vtlo : vthi)
                + ((size_t)bh * D_ + r) * S_ + j0 + ch * 32 + seg * 8;
            cp16(sbase + FA_V0 + st * 20480 + t * 10240 + ch * 5120
                 + r * 80 + seg * 16, src);
        }
    };
    load_kv(0);
    asm volatile("cp.async.commit_group;" ::: "memory");

    float ctx[2][4][4];
    #pragma unroll
    for (int a = 0; a < 2; a++)
        #pragma unroll
        for (int b = 0; b < 4; b++)
            #pragma unroll
            for (int q = 0; q < 4; q++) ctx[a][b][q] = 0.0f;

    for (int j = 0; j < 32; j++) {
        const int st = j & 1, j0 = j * 64;
        if (j + 1 < 32) {
            load_kv(j + 1);
            asm volatile("cp.async.commit_group;" ::: "memory");
            asm volatile("cp.async.wait_group 1;" ::: "memory");
        } else {
            asm volatile("cp.async.wait_group 0;" ::: "memory");
        }
        __syncthreads();   // K/V stage ready; prior AV reads of P complete

        // ---- QK: s = q . k  (fp16 2-term) ----
        float accs[2][4][4];
        #pragma unroll
        for (int a = 0; a < 2; a++)
            #pragma unroll
            for (int b = 0; b < 4; b++)
                #pragma unroll
                for (int q = 0; q < 4; q++) accs[a][b][q] = 0.0f;
        #pragma unroll
        for (int it = 0; it < 2; it++) {
            #pragma unroll
            for (int kk = 0; kk < 2; kk++) {
                uint32_t ah[2][4];
                #pragma unroll
                for (int mi = 0; mi < 2; mi++) {
                    uint32_t addr = sbase + FA_Q0 + it * 10240
                        + ((m0w + mi * 16 + (lane & 15)) * 40
                           + kk * 16 + ((lane >> 4) << 3)) * 2;
                    LDSM4(ah[mi], addr);
                }
                uint32_t bhf[4][2], blf[4][2];
                #pragma unroll
                for (int nj = 0; nj < 2; nj++) {
                    uint32_t row = n0w + nj * 16 + (lane & 7) + ((lane >> 4) << 3);
                    uint32_t col = kk * 16 + (((lane >> 3) & 1) << 3);
                    uint32_t addr = sbase + FA_K0 + st * 20480 + it * 5120
                        + (row * 40 + col) * 2;
                    uint32_t t4[4];
                    LDSM4(t4, addr);
                    bhf[2 * nj][0] = t4[0]; bhf[2 * nj][1] = t4[1];
                    bhf[2 * nj + 1][0] = t4[2]; bhf[2 * nj + 1][1] = t4[3];
                    LDSM4(t4, addr + 10240);
                    blf[2 * nj][0] = t4[0]; blf[2 * nj][1] = t4[1];
                    blf[2 * nj + 1][0] = t4[2]; blf[2 * nj + 1][1] = t4[3];
                }
                #pragma unroll
                for (int mi = 0; mi < 2; mi++)
                    #pragma unroll
                    for (int ni = 0; ni < 4; ni++) {
                        MMA_F16(accs[mi][ni], ah[mi], bhf[ni][0], bhf[ni][1]);
                        MMA_F16(accs[mi][ni], ah[mi], blf[ni][0], blf[ni][1]);
                    }
            }
        }

        // ---- P: p = exp(0.125 s) * rinv; write weights + fp16 P smem ----
        #pragma unroll
        for (int mi = 0; mi < 2; mi++)
            #pragma unroll
            for (int ni = 0; ni < 4; ni++) {
                int row0 = m0w + mi * 16 + (lane >> 2);
                int col  = n0w + ni * 8 + ((lane & 3) << 1);
                #pragma unroll
                for (int rr = 0; rr < 2; rr++) {
                    int row = row0 + rr * 8;
                    float p0 = fast_exp(accs[mi][ni][rr * 2 + 0] * 0.125f) * s_r[row];
                    float p1 = fast_exp(accs[mi][ni][rr * 2 + 1] * 0.125f) * s_r[row];
                    float2 w2; w2.x = p0; w2.y = p1;
                    *(float2*)(Wbuf + ((size_t)bh * S_ + i0 + row) * S_ + j0 + col) = w2;
                    __half2 hp = __floats2half2_rn(p0, p1);
                    int ch = col >> 5, c32 = col & 31;
                    *(uint32_t*)(smem + FA_P0 + ch * 10240 + row * 80 + c32 * 2)
                        = *(uint32_t*)&hp;
                }
            }
        __syncthreads();   // P visible before AV reads

        // ---- AV: ctx += p . v  (fp16 2-term) ----
        #pragma unroll
        for (int it = 0; it < 2; it++) {
            #pragma unroll
            for (int kk = 0; kk < 2; kk++) {
                uint32_t ah[2][4];
                #pragma unroll
                for (int mi = 0; mi < 2; mi++) {
                    uint32_t addr = sbase + FA_P0 + it * 10240
                        + ((m0w + mi * 16 + (lane & 15)) * 40
                           + kk * 16 + ((lane >> 4) << 3)) * 2;
                    LDSM4(ah[mi], addr);
                }
                uint32_t bhf[4][2], blf[4][2];
                #pragma unroll
                for (int nj = 0; nj < 2; nj++) {
                    uint32_t row = n0w + nj * 16 + (lane & 7) + ((lane >> 4) << 3);
                    uint32_t col = kk * 16 + (((lane >> 3) & 1) << 3);
                    uint32_t addr = sbase + FA_V0 + st * 20480 + it * 5120
                        + (row * 40 + col) * 2;
                    uint32_t t4[4];
                    LDSM4(t4, addr);
                    bhf[2 * nj][0] = t4[0]; bhf[2 * nj][1] = t4[1];
                    bhf[2 * nj + 1][0] = t4[2]; bhf[2 * nj + 1][1] = t4[3];
                    LDSM4(t4, addr + 10240);
                    blf[2 * nj][0] = t4[0]; blf[2 * nj][1] = t4[1];
                    blf[2 * nj + 1][0] = t4[2]; blf[2 * nj + 1][1] = t4[3];
                }
                #pragma unroll
                for (int mi = 0; mi < 2; mi++)
                    #pragma unroll
                    for (int ni = 0; ni < 4; ni++) {
                        MMA_F16(ctx[mi][ni], ah[mi], bhf[ni][0], bhf[ni][1]);
                        MMA_F16(ctx[mi][ni], ah[mi], blf[ni][0], blf[ni][1]);
                    }
            }
        }
    }

    // ---- epilogue: ctx -> fp16 row-major [token][E] at col hh*64+d ----
    #pragma unroll
    for (int mi = 0; mi < 2; mi++)
        #pragma unroll
        for (int ni = 0; ni < 4; ni++) {
            int row0 = m0w + mi * 16 + (lane >> 2);
            int col  = n0w + ni * 8 + ((lane & 3) << 1);
            #pragma unroll
            for (int rr = 0; rr < 2; rr++) {
                int row = row0 + rr * 8;
                size_t token = (size_t)bb * S_ + i0 + row;
                size_t o = (token * E_ + hh * 64 + col) >> 1;
                ((__half2*)ctxh)[o] =
                    __floats2half2_rn(ctx[mi][ni][rr * 2 + 0],
                                      ctx[mi][ni][rr * 2 + 1]);
            }
        }
}

// ================= conversions ===========================================
__global__ __launch_bounds__(256) void conv_hilo4_kernel(
    const float4* __restrict__ in, __nv_bfloat162* __restrict__ hi,
    __nv_bfloat162* __restrict__ lo, int n4)
{
    int i = blockIdx.x * 256 + threadIdx.x;
    if (i < n4) {
        float4 v = in[i];
        __nv_bfloat162 h01 = __floats2bfloat162_rn(v.x, v.y);
        __nv_bfloat162 h23 = __floats2bfloat162_rn(v.z, v.w);
        hi[2 * i]     = h01;
        hi[2 * i + 1] = h23;
        lo[2 * i]     = __floats2bfloat162_rn(v.x - __bfloat162float(h01.x),
                                              v.y - __bfloat162float(h01.y));
        lo[2 * i + 1] = __floats2bfloat162_rn(v.z - __bfloat162float(h23.x),
                                              v.w - __bfloat162float(h23.y));
    }
}

__global__ __launch_bounds__(256) void transconv_bf_kernel(
    const float* __restrict__ W, __nv_bfloat16* __restrict__ hi,
    __nv_bfloat16* __restrict__ lo, int K, int N)
{
    __shared__ float t[32][33];
    const int k0 = blockIdx.y * 32, n0 = blockIdx.x * 32;
    const int tx = threadIdx.x & 31, ty = threadIdx.x >> 5;
    #pragma unroll
    for (int i = 0; i < 32; i += 8)
        t[ty + i][tx] = W[(size_t)(k0 + ty + i) * N + n0 + tx];
    __syncthreads();
    #pragma unroll
    for (int i = 0; i < 32; i += 8) {
        float x = t[tx][ty + i];
        __nv_bfloat16 h = __float2bfloat16(x);
        size_t o = (size_t)(n0 + ty + i) * K + k0 + tx;
        hi[o] = h;
        lo[o] = __float2bfloat16(x - __bfloat162float(h));
    }
}

__global__ __launch_bounds__(256) void transconv_h_kernel(
    const float* __restrict__ W, __half* __restrict__ hi,
    __half* __restrict__ lo, int K, int N)
{
    __shared__ float t[32][33];
    const int k0 = blockIdx.y * 32, n0 = blockIdx.x * 32;
    const int tx = threadIdx.x & 31, ty = threadIdx.x >> 5;
    #pragma unroll
    for (int i = 0; i < 32; i += 8)
        t[ty + i][tx] = W[(size_t)(k0 + ty + i) * N + n0 + tx];
    __syncthreads();
    #pragma unroll
    for (int i = 0; i < 32; i += 8) {
        float x = t[tx][ty + i];
        __half h = __float2half_rn(x);
        size_t o = (size_t)(n0 + ty + i) * K + k0 + tx;
        hi[o] = h;
        lo[o] = __float2half_rn(x - __half2float(h));
    }
}

__global__ __launch_bounds__(256) void transpose16_kernel(
    const uint16_t* __restrict__ hi_in, const uint16_t* __restrict__ lo_in,
    uint16_t* __restrict__ hi_out, uint16_t* __restrict__ lo_out)
{
    __shared__ uint16_t th[32][33];
    __shared__ uint16_t tl[32][33];
    const int bh = blockIdx.z;
    const int s0 = blockIdx.x * 32, d0 = blockIdx.y * 32;
    const int tx = threadIdx.x & 31, ty = threadIdx.x >> 5;
    #pragma unroll
    for (int i = 0; i < 32; i += 8) {
        size_t src = ((size_t)bh * S_ + s0 + ty + i) * D_ + d0 + tx;
        th[ty + i][tx] = hi_in[src];
        tl[ty + i][tx] = lo_in[src];
    }
    __syncthreads();
    #pragma unroll
    for (int i = 0; i < 32; i += 8) {
        size_t dst = ((size_t)bh * D_ + d0 + ty + i) * S_ + s0 + tx;
        hi_out[dst] = th[tx][ty + i];
        lo_out[dst] = tl[tx][ty + i];
    }
}

// ---------------- launch ----------------
extern "C" void kernel_launch(void* const* d_in, const int* in_sizes, int n_in,
                              void* d_out, int out_size)
{
    const float* query = (const float*)d_in[0];
    const float* key   = (const float*)d_in[1];
    const float* value = (const float*)d_in[2];
    const float* Wq    = (const float*)d_in[3];
    const float* bq    = (const float*)d_in[4];
    const float* Wk    = (const float*)d_in[5];
    const float* bk    = (const float*)d_in[6];
    const float* Wv    = (const float*)d_in[7];
    const float* bv    = (const float*)d_in[8];
    const float* Wo    = (const float*)d_in[9];
    const float* bo    = (const float*)d_in[10];

    float* out  = (float*)d_out;                 // [B,S,E]
    float* Wbuf = out + (size_t)M_ * E_;         // [B,H,S,S]

    __nv_bfloat16 *ahi, *alo, *whi, *wlo;
    __half *wohi, *wolo, *qhi, *khi, *klo, *vhi, *vlo, *vthi, *vtlo, *ctxh;
    float *gps, *gri;
    cudaGetSymbolAddress((void**)&ahi,  g_Ahi);
    cudaGetSymbolAddress((void**)&alo,  g_Alo);
    cudaGetSymbolAddress((void**)&whi,  g_Whi);
    cudaGetSymbolAddress((void**)&wlo,  g_Wlo);
    cudaGetSymbolAddress((void**)&wohi, g_Wohi);
    cudaGetSymbolAddress((void**)&wolo, g_Wolo);
    cudaGetSymbolAddress((void**)&qhi,  g_qhi);
    cudaGetSymbolAddress((void**)&khi,  g_khi);
    cudaGetSymbolAddress((void**)&klo,  g_klo);
    cudaGetSymbolAddress((void**)&vhi,  g_vhi);
    cudaGetSymbolAddress((void**)&vlo,  g_vlo);
    cudaGetSymbolAddress((void**)&vthi, g_vthi);
    cudaGetSymbolAddress((void**)&vtlo, g_vtlo);
    cudaGetSymbolAddress((void**)&ctxh, g_ctxh);
    cudaGetSymbolAddress((void**)&gps,  g_psum);
    cudaGetSymbolAddress((void**)&gri,  g_rinv);

    const int SMEM_PROJ = 2 * (2 * 128 * 80 + 2 * 128 * 80);  // 81920
    const int SMEM_H16  = 2 * (1 * 128 * 80 + 2 * 128 * 80);  // 61440
    cudaFuncSetAttribute(hilo_gemm<128, 0, 1>,
                         cudaFuncAttributeMaxDynamicSharedMemorySize, SMEM_PROJ);
    cudaFuncSetAttribute(hilo_gemm<128, 1, 4>,
                         cudaFuncAttributeMaxDynamicSharedMemorySize, SMEM_H16);
    cudaFuncSetAttribute(hilo_gemm<128, 1, 0>,
                         cudaFuncAttributeMaxDynamicSharedMemorySize, SMEM_H16);
    cudaFuncSetAttribute(flash_av_kernel,
                         cudaFuncAttributeMaxDynamicSharedMemorySize, FA_SMEM);

    // ---- projections (bf16 3-term, write head-major fp16 hi/lo) ----
    conv_hilo4_kernel<<<(M_ * QD_ / 4 + 255) / 256, 256>>>(
        (const float4*)query, (__nv_bfloat162*)ahi, (__nv_bfloat162*)alo, M_ * QD_ / 4);
    transconv_bf_kernel<<<dim3(E_ / 32, QD_ / 32), 256>>>(Wq, whi, wlo, QD_, E_);
    hilo_gemm<128, 0, 1><<<dim3(E_ / 128, M_ / 128, 1), 256, SMEM_PROJ>>>(
        ahi, alo, whi, wlo, bq, nullptr, qhi, nullptr, nullptr,
        QD_, QD_, QD_, E_, 0, 0, 0, 0, 1, 1.0f);

    conv_hilo4_kernel<<<(M_ * KD_ / 4 + 255) / 256, 256>>>(
        (const float4*)key, (__nv_bfloat162*)ahi, (__nv_bfloat162*)alo, M_ * KD_ / 4);
    transconv_bf_kernel<<<dim3(E_ / 32, KD_ / 32), 256>>>(Wk, whi, wlo, KD_, E_);
    hilo_gemm<128, 0, 1><<<dim3(E_ / 128, M_ / 128, 1), 256, SMEM_PROJ>>>(
        ahi, alo, whi, wlo, bk, nullptr, khi, klo, nullptr,
        KD_, KD_, KD_, E_, 0, 0, 0, 0, 1, 1.0f);

    conv_hilo4_kernel<<<(M_ * VD_ / 4 + 255) / 256, 256>>>(
        (const float4*)value, (__nv_bfloat162*)ahi, (__nv_bfloat162*)alo, M_ * VD_ / 4);
    transconv_bf_kernel<<<dim3(E_ / 32, VD_ / 32), 256>>>(Wv, whi, wlo, VD_, E_);
    hilo_gemm<128, 0, 1><<<dim3(E_ / 128, M_ / 128, 1), 256, SMEM_PROJ>>>(
        ahi, alo, whi, wlo, bv, nullptr, vhi, vlo, nullptr,
        VD_, VD_, VD_, E_, 0, 0, 0, 0, 1, 1.0f);

    transpose16_kernel<<<dim3(S_ / 32, D_ / 32, BH_), 256>>>(
        (const uint16_t*)vhi, (const uint16_t*)vlo,
        (uint16_t*)vthi, (uint16_t*)vtlo);

    // ---- pass 1: row-sum stats only (no score materialization) ----
    hilo_gemm<128, 1, 4><<<dim3(S_ / 128, S_ / 128, BH_), 256, SMEM_H16>>>(
        qhi, nullptr, khi, klo, nullptr, nullptr, nullptr, nullptr, gps,
        D_, D_, D_, S_,
        (long long)S_ * D_, (long long)S_ * D_,
        0, 0, 1, 0.125f);

    combine_kernel<<<(BH_ * S_) / 256, 256>>>(gps, gri);

    // ---- pass 2: fused QK recompute + weights write + AV ----
    flash_av_kernel<<<dim3(S_ / 128, BH_), 256, FA_SMEM>>>(
        qhi, khi, klo, vthi, vtlo, gri, Wbuf, ctxh);

    // ---- output projection: fp16 2-term (A = ctx fp16) ----
    transconv_h_kernel<<<dim3(E_ / 32, E_ / 32), 256>>>(Wo, wohi, wolo, E_, E_);
    hilo_gemm<128, 1, 0><<<dim3(E_ / 128, M_ / 128, 1), 256, SMEM_H16>>>(
        ctxh, nullptr, wohi, wolo, bo, out, nullptr, nullptr, nullptr,
        E_, E_, E_, E_, 0, 0, 0, 0, 1, 1.0f);
}

// round 14
// speedup vs baseline: 1.2121x; 1.0870x over previous
#include <cuda_runtime.h>
#include <cuda_fp16.h>
#include <cstdint>

#define B_   4
#define S_   2048
#define E_   1024
#define H_   16
#define D_   64
#define QD_  1024
#define KD_  768
#define VD_  768
#define M_   (B_ * S_)          // 8192
#define BH_  (B_ * H_)          // 64

// ---------------- device scratch (no allocations allowed) ----------------
__device__ __align__(16) __half g_Ahf[M_ * E_];
__device__ __align__(16) __half g_Wohi[E_ * E_];
__device__ __align__(16) __half g_Wolo[E_ * E_];
__device__ __align__(16) __half g_qhi[BH_ * S_ * D_];
__device__ __align__(16) __half g_khi[BH_ * S_ * D_];
__device__ __align__(16) __half g_klo[BH_ * S_ * D_];
__device__ __align__(16) __half g_vhi[BH_ * S_ * D_];
__device__ __align__(16) __half g_vlo[BH_ * S_ * D_];
__device__ __align__(16) __half g_vthi[BH_ * D_ * S_];
__device__ __align__(16) __half g_vtlo[BH_ * D_ * S_];
__device__ __align__(16) __half g_ctxh[M_ * E_];
__device__ float g_psum[BH_ * 16 * S_];
__device__ float g_rinv[BH_ * S_];

// ======================= helpers ============================
__device__ __forceinline__ uint32_t smem_u32(const void* p) {
    uint32_t a;
    asm("{ .reg .u64 t; cvta.to.shared.u64 t, %1; cvt.u32.u64 %0, t; }"
        : "=r"(a) : "l"(p));
    return a;
}
__device__ __forceinline__ void cp16(uint32_t dst, const void* src) {
    asm volatile("cp.async.cg.shared.global [%0], [%1], 16;" :: "r"(dst), "l"(src));
}
#define LDSM4(R, addr) \
    asm volatile("ldmatrix.sync.aligned.m8n8.x4.shared.b16 {%0,%1,%2,%3}, [%4];" \
                 : "=r"((R)[0]), "=r"((R)[1]), "=r"((R)[2]), "=r"((R)[3]) : "r"(addr))
#define MMA_F16(c, a, b0, b1) \
    asm volatile("mma.sync.aligned.m16n8k16.row.col.f32.f16.f16.f32 " \
                 "{%0,%1,%2,%3}, {%4,%5,%6,%7}, {%8,%9}, {%0,%1,%2,%3};" \
                 : "+f"((c)[0]), "+f"((c)[1]), "+f"((c)[2]), "+f"((c)[3]) \
                 : "r"((a)[0]), "r"((a)[1]), "r"((a)[2]), "r"((a)[3]), "r"(b0), "r"(b1))

__device__ __forceinline__ float fast_exp(float x) {
    float t = x * 1.44269504088896341f;
    t = fmaxf(t, -125.0f);
    float r = t + 12582912.0f;
    int   n = __float_as_int(r) - 0x4B400000;
    float f = t - (r - 12582912.0f);
    float p = 1.33336498e-3f;
    p = fmaf(p, f, 9.61011466e-3f);
    p = fmaf(p, f, 5.55036595e-2f);
    p = fmaf(p, f, 2.40226510e-1f);
    p = fmaf(p, f, 6.93147182e-1f);
    p = fmaf(p, f, 1.0f);
    return __int_as_float((n + 127) << 23) * p;
}

// fp32 pair -> fp16 hi/lo pair at half2-element index o (lo optional)
__device__ __forceinline__ void store_hl_h2(
    void* Ohi, void* Olo, size_t o, float x0, float x1)
{
    __half2 hh = __floats2half2_rn(x0, x1);
    ((__half2*)Ohi)[o] = hh;
    if (Olo) {
        float l0 = x0 - __half2float(__low2half(hh));
        float l1 = x1 - __half2float(__high2half(hh));
        ((__half2*)Olo)[o] = __floats2half2_rn(l0, l1);
    }
}

// ================= fp16 2-term split tensor-core GEMM ====================
// C = A·Bh + A·Bl ; A: [M,K] fp16, B: [N,K] fp16 hi/lo.
// Tiles 128 x 128, BK=32, 2-stage cp.async.
// EPI 0: fp32 C (+bias, alpha)
// EPI 1: fp16 hi/lo head-major [bh][s][d] (+bias); Olo optional
// EPI 4: stats only — per-(row,colblock) sums of exp(alpha*acc) to gps, no C
template<int EPI>
__global__ __launch_bounds__(256) void h2term_gemm(
    const __half* __restrict__ A_, const __half* __restrict__ Bhi_,
    const __half* __restrict__ Blo_,
    const float* __restrict__ bias, float* __restrict__ C,
    void* __restrict__ Ohi, void* __restrict__ Olo,
    float* __restrict__ gps,
    int K, int ldA, int ldB, int ldC,
    long long strideA, long long strideB, long long sCo, float alpha)
{
    constexpr int SSA = 128 * 80;
    constexpr int BOF = 128 * 80;
    constexpr int SS  = SSA + 2 * BOF;
    extern __shared__ __align__(16) char smem[];
    const uint32_t sbase = smem_u32(smem);

    const int tid  = threadIdx.x;
    const int lane = tid & 31;
    const int wid  = tid >> 5;
    const int m0w  = (wid >> 1) * 32;
    const int n0w  = (wid & 1) * 64;
    const int m0   = blockIdx.y * 128;
    const int n0   = blockIdx.x * 128;
    const size_t z = blockIdx.z;

    const uint16_t* Ah16 = (const uint16_t*)A_ + z * strideA + (size_t)m0 * ldA;
    const uint16_t* Bh = (const uint16_t*)Bhi_ + z * strideB + (size_t)n0 * ldB;
    const uint16_t* Bl = (const uint16_t*)Blo_ + z * strideB + (size_t)n0 * ldB;

    const int T = K / 32;
    float acc[2][8][4];
    #pragma unroll
    for (int i = 0; i < 2; i++)
        #pragma unroll
        for (int j = 0; j < 8; j++)
            #pragma unroll
            for (int q = 0; q < 4; q++) acc[i][j][q] = 0.0f;

    auto load_stage = [&](int it) {
        const uint32_t sb = sbase + (it & 1) * SS;
        const int k0 = it * 32;
        #pragma unroll
        for (int c = tid; c < 1024; c += 256) {
            int tile = (c >= 512) ? 1 : 0;
            int cc   = c - tile * 512;
            int r    = cc >> 2, seg = cc & 3;
            const uint16_t* src = (tile ? Bl : Bh) + (size_t)r * ldB + k0 + seg * 8;
            cp16(sb + SSA + tile * BOF + r * 80 + seg * 16, src);
        }
        #pragma unroll
        for (int c = tid; c < 512; c += 256) {
            int r = c >> 2, seg = c & 3;
            cp16(sb + r * 80 + seg * 16, Ah16 + (size_t)r * ldA + k0 + seg * 8);
        }
    };

    auto do_mmas = [&](int it) {
        const uint32_t sA = sbase + (it & 1) * SS;
        const uint32_t sB = sA + SSA;
        #pragma unroll
        for (int kk = 0; kk < 2; kk++) {
            uint32_t ah[2][4];
            #pragma unroll
            for (int mi = 0; mi < 2; mi++) {
                uint32_t addr = sA + ((m0w + mi * 16 + (lane & 15)) * 40
                                      + kk * 16 + ((lane >> 4) << 3)) * 2;
                LDSM4(ah[mi], addr);
            }
            uint32_t bh[8][2], bl[8][2];
            #pragma unroll
            for (int nj = 0; nj < 4; nj++) {
                uint32_t row = n0w + nj * 16 + (lane & 7) + ((lane >> 4) << 3);
                uint32_t col = kk * 16 + (((lane >> 3) & 1) << 3);
                uint32_t addr = sB + (row * 40 + col) * 2;
                uint32_t t4[4];
                LDSM4(t4, addr);
                bh[2 * nj][0] = t4[0]; bh[2 * nj][1] = t4[1];
                bh[2 * nj + 1][0] = t4[2]; bh[2 * nj + 1][1] = t4[3];
                LDSM4(t4, addr + BOF);
                bl[2 * nj][0] = t4[0]; bl[2 * nj][1] = t4[1];
                bl[2 * nj + 1][0] = t4[2]; bl[2 * nj + 1][1] = t4[3];
            }
            #pragma unroll
            for (int mi = 0; mi < 2; mi++)
                #pragma unroll
                for (int ni = 0; ni < 8; ni++) {
                    MMA_F16(acc[mi][ni], ah[mi], bh[ni][0], bh[ni][1]);
                    MMA_F16(acc[mi][ni], ah[mi], bl[ni][0], bl[ni][1]);
                }
        }
    };

    load_stage(0);
    asm volatile("cp.async.commit_group;" ::: "memory");
    for (int it = 0; it < T; it++) {
        if (it + 1 < T) {
            load_stage(it + 1);
            asm volatile("cp.async.commit_group;" ::: "memory");
            asm volatile("cp.async.wait_group 1;" ::: "memory");
        } else {
            asm volatile("cp.async.wait_group 0;" ::: "memory");
        }
        __syncthreads();
        do_mmas(it);
        __syncthreads();
    }

    // ---------------- epilogue ----------------
    if (EPI == 0) {
        #pragma unroll
        for (int mi = 0; mi < 2; mi++)
            #pragma unroll
            for (int ni = 0; ni < 8; ni++) {
                int row = m0 + m0w + mi * 16 + (lane >> 2);
                int col = n0 + n0w + ni * 8 + ((lane & 3) << 1);
                float b0 = bias ? __ldg(bias + col) : 0.0f;
                float b1 = bias ? __ldg(bias + col + 1) : 0.0f;
                C[(size_t)row * ldC + col]           = acc[mi][ni][0] * alpha + b0;
                C[(size_t)row * ldC + col + 1]       = acc[mi][ni][1] * alpha + b1;
                C[(size_t)(row + 8) * ldC + col]     = acc[mi][ni][2] * alpha + b0;
                C[(size_t)(row + 8) * ldC + col + 1] = acc[mi][ni][3] * alpha + b1;
            }
    } else if (EPI == 1) {
        #pragma unroll
        for (int mi = 0; mi < 2; mi++)
            #pragma unroll
            for (int ni = 0; ni < 8; ni++) {
                int row = m0 + m0w + mi * 16 + (lane >> 2);
                int col = n0 + n0w + ni * 8 + ((lane & 3) << 1);
                float b0 = bias ? __ldg(bias + col) : 0.0f;
                float b1 = bias ? __ldg(bias + col + 1) : 0.0f;
                int h = col >> 6, d = col & 63;
                #pragma unroll
                for (int rr = 0; rr < 2; rr++) {
                    int r = row + rr * 8;
                    int b = r >> 11, s = r & 2047;
                    size_t o = ((((size_t)(b * 16 + h)) * S_ + s) * D_ + d) >> 1;
                    store_hl_h2(Ohi, Olo, o,
                                acc[mi][ni][rr * 2 + 0] + b0,
                                acc[mi][ni][rr * 2 + 1] + b1);
                }
            }
    } else {
        // EPI == 4: row-sum partials of exp(alpha*acc); no C write
        __shared__ float ps_s[128][2];
        float rs[2][2] = {{0.0f, 0.0f}, {0.0f, 0.0f}};
        #pragma unroll
        for (int mi = 0; mi < 2; mi++)
            #pragma unroll
            for (int ni = 0; ni < 8; ni++) {
                rs[mi][0] += fast_exp(acc[mi][ni][0] * alpha)
                           + fast_exp(acc[mi][ni][1] * alpha);
                rs[mi][1] += fast_exp(acc[mi][ni][2] * alpha)
                           + fast_exp(acc[mi][ni][3] * alpha);
            }
        #pragma unroll
        for (int mi = 0; mi < 2; mi++)
            #pragma unroll
            for (int rr = 0; rr < 2; rr++) {
                float v = rs[mi][rr];
                v += __shfl_xor_sync(0xFFFFFFFFu, v, 1);
                v += __shfl_xor_sync(0xFFFFFFFFu, v, 2);
                rs[mi][rr] = v;
            }
        if ((lane & 3) == 0) {
            #pragma unroll
            for (int mi = 0; mi < 2; mi++)
                #pragma unroll
                for (int rr = 0; rr < 2; rr++)
                    ps_s[m0w + mi * 16 + (lane >> 2) + rr * 8][wid & 1] = rs[mi][rr];
        }
        __syncthreads();
        if (tid < 128) {
            size_t o = ((size_t)z * gridDim.x + blockIdx.x) * (size_t)S_ + m0 + tid;
            gps[o] = ps_s[tid][0] + ps_s[tid][1];
        }
    }
}

// ---------------- combine: rinv = 1 / sum of 16 col-block partials -------
__global__ __launch_bounds__(256) void combine_kernel(
    const float* __restrict__ gps, float* __restrict__ rinv)
{
    int g = blockIdx.x * 256 + threadIdx.x;
    int bh = g >> 11, r = g & 2047;
    const float* ps = gps + (size_t)bh * 16 * S_ + r;
    float s = 0.0f;
    #pragma unroll
    for (int jb = 0; jb < 16; jb++) s += ps[(size_t)jb * S_];
    rinv[g] = 1.0f / s;
}

// ================= flash attention: QK recompute + P write + AV ==========
#define FA_Q0   0
#define FA_K0   20480
#define FA_V0   61440
#define FA_P0   102400
#define FA_SMEM 122880
__global__ __launch_bounds__(256) void flash_av_kernel(
    const __half* __restrict__ qh,
    const __half* __restrict__ khi, const __half* __restrict__ klo,
    const __half* __restrict__ vthi, const __half* __restrict__ vtlo,
    const float* __restrict__ rinv, float* __restrict__ Wbuf,
    __half* __restrict__ ctxh)
{
    extern __shared__ __align__(16) char smem[];
    const uint32_t sbase = smem_u32(smem);
    __shared__ float s_r[128];

    const int tid  = threadIdx.x;
    const int lane = tid & 31;
    const int wid  = tid >> 5;
    const int m0w  = (wid >> 1) * 32;
    const int n0w  = (wid & 1) * 32;
    const int i0   = blockIdx.x * 128;
    const int bh   = blockIdx.y;
    const int bb   = bh >> 4, hh = bh & 15;

    if (tid < 128) s_r[tid] = rinv[(size_t)bh * S_ + i0 + tid];

    const __half* qg = qh + ((size_t)bh * S_ + i0) * D_;
    #pragma unroll
    for (int l = 0; l < 4; l++) {
        int c = tid + l * 256;
        int it = c >> 9, cc = c & 511, r = cc >> 2, seg = cc & 3;
        cp16(sbase + FA_Q0 + it * 10240 + r * 80 + seg * 16,
             qg + (size_t)r * D_ + it * 32 + seg * 8);
    }
    auto load_kv = [&](int j) {
        const int st = j & 1, j0 = j * 64;
        #pragma unroll
        for (int l = 0; l < 4; l++) {
            int c = tid + l * 256;
            int t = c >> 9, cc = c & 511;
            int r = cc >> 3, rem = cc & 7, ch = rem >> 2, seg = rem & 3;
            const __half* src = (t ? klo : khi)
                + ((size_t)bh * S_ + j0 + r) * D_ + ch * 32 + seg * 8;
            cp16(sbase + FA_K0 + st * 20480 + t * 10240 + ch * 5120
                 + r * 80 + seg * 16, src);
        }
        #pragma unroll
        for (int l = 0; l < 4; l++) {
            int c = tid + l * 256;
            int t = c >> 9, cc = c & 511;
            int r = cc >> 3, rem = cc & 7, ch = rem >> 2, seg = rem & 3;
            const __half* src = (t ? vtlo : vthi)
                + ((size_t)bh * D_ + r) * S_ + j0 + ch * 32 + seg * 8;
            cp16(sbase + FA_V0 + st * 20480 + t * 10240 + ch * 5120
                 + r * 80 + seg * 16, src);
        }
    };
    load_kv(0);
    asm volatile("cp.async.commit_group;" ::: "memory");

    float ctx[2][4][4];
    #pragma unroll
    for (int a = 0; a < 2; a++)
        #pragma unroll
        for (int b = 0; b < 4; b++)
            #pragma unroll
            for (int q = 0; q < 4; q++) ctx[a][b][q] = 0.0f;

    for (int j = 0; j < 32; j++) {
        const int st = j & 1, j0 = j * 64;
        if (j + 1 < 32) {
            load_kv(j + 1);
            asm volatile("cp.async.commit_group;" ::: "memory");
            asm volatile("cp.async.wait_group 1;" ::: "memory");
        } else {
            asm volatile("cp.async.wait_group 0;" ::: "memory");
        }
        __syncthreads();

        float accs[2][4][4];
        #pragma unroll
        for (int a = 0; a < 2; a++)
            #pragma unroll
            for (int b = 0; b < 4; b++)
                #pragma unroll
                for (int q = 0; q < 4; q++) accs[a][b][q] = 0.0f;
        #pragma unroll
        for (int it = 0; it < 2; it++) {
            #pragma unroll
            for (int kk = 0; kk < 2; kk++) {
                uint32_t ah[2][4];
                #pragma unroll
                for (int mi = 0; mi < 2; mi++) {
                    uint32_t addr = sbase + FA_Q0 + it * 10240
                        + ((m0w + mi * 16 + (lane & 15)) * 40
                           + kk * 16 + ((lane >> 4) << 3)) * 2;
                    LDSM4(ah[mi], addr);
                }
                uint32_t bhf[4][2], blf[4][2];
                #pragma unroll
                for (int nj = 0; nj < 2; nj++) {
                    uint32_t row = n0w + nj * 16 + (lane & 7) + ((lane >> 4) << 3);
                    uint32_t col = kk * 16 + (((lane >> 3) & 1) << 3);
                    uint32_t addr = sbase + FA_K0 + st * 20480 + it * 5120
                        + (row * 40 + col) * 2;
                    uint32_t t4[4];
                    LDSM4(t4, addr);
                    bhf[2 * nj][0] = t4[0]; bhf[2 * nj][1] = t4[1];
                    bhf[2 * nj + 1][0] = t4[2]; bhf[2 * nj + 1][1] = t4[3];
                    LDSM4(t4, addr + 10240);
                    blf[2 * nj][0] = t4[0]; blf[2 * nj][1] = t4[1];
                    blf[2 * nj + 1][0] = t4[2]; blf[2 * nj + 1][1] = t4[3];
                }
                #pragma unroll
                for (int mi = 0; mi < 2; mi++)
                    #pragma unroll
                    for (int ni = 0; ni < 4; ni++) {
                        MMA_F16(accs[mi][ni], ah[mi], bhf[ni][0], bhf[ni][1]);
                        MMA_F16(accs[mi][ni], ah[mi], blf[ni][0], blf[ni][1]);
                    }
            }
        }

        #pragma unroll
        for (int mi = 0; mi < 2; mi++)
            #pragma unroll
            for (int ni = 0; ni < 4; ni++) {
                int row0 = m0w + mi * 16 + (lane >> 2);
                int col  = n0w + ni * 8 + ((lane & 3) << 1);
                #pragma unroll
                for (int rr = 0; rr < 2; rr++) {
                    int row = row0 + rr * 8;
                    float p0 = fast_exp(accs[mi][ni][rr * 2 + 0] * 0.125f) * s_r[row];
                    float p1 = fast_exp(accs[mi][ni][rr * 2 + 1] * 0.125f) * s_r[row];
                    float2 w2; w2.x = p0; w2.y = p1;
                    *(float2*)(Wbuf + ((size_t)bh * S_ + i0 + row) * S_ + j0 + col) = w2;
                    __half2 hp = __floats2half2_rn(p0, p1);
                    int ch = col >> 5, c32 = col & 31;
                    *(uint32_t*)(smem + FA_P0 + ch * 10240 + row * 80 + c32 * 2)
                        = *(uint32_t*)&hp;
                }
            }
        __syncthreads();

        #pragma unroll
        for (int it = 0; it < 2; it++) {
            #pragma unroll
            for (int kk = 0; kk < 2; kk++) {
                uint32_t ah[2][4];
                #pragma unroll
                for (int mi = 0; mi < 2; mi++) {
                    uint32_t addr = sbase + FA_P0 + it * 10240
                        + ((m0w + mi * 16 + (lane & 15)) * 40
                           + kk * 16 + ((lane >> 4) << 3)) * 2;
                    LDSM4(ah[mi], addr);
                }
                uint32_t bhf[4][2], blf[4][2];
                #pragma unroll
                for (int nj = 0; nj < 2; nj++) {
                    uint32_t row = n0w + nj * 16 + (lane & 7) + ((lane >> 4) << 3);
                    uint32_t col = kk * 16 + (((lane >> 3) & 1) << 3);
                    uint32_t addr = sbase + FA_V0 + st * 20480 + it * 5120
                        + (row * 40 + col) * 2;
                    uint32_t t4[4];
                    LDSM4(t4, addr);
                    bhf[2 * nj][0] = t4[0]; bhf[2 * nj][1] = t4[1];
                    bhf[2 * nj + 1][0] = t4[2]; bhf[2 * nj + 1][1] = t4[3];
                    LDSM4(t4, addr + 10240);
                    blf[2 * nj][0] = t4[0]; blf[2 * nj][1] = t4[1];
                    blf[2 * nj + 1][0] = t4[2]; blf[2 * nj + 1][1] = t4[3];
                }
                #pragma unroll
                for (int mi = 0; mi < 2; mi++)
                    #pragma unroll
                    for (int ni = 0; ni < 4; ni++) {
                        MMA_F16(ctx[mi][ni], ah[mi], bhf[ni][0], bhf[ni][1]);
                        MMA_F16(ctx[mi][ni], ah[mi], blf[ni][0], blf[ni][1]);
                    }
            }
        }
    }

    #pragma unroll
    for (int mi = 0; mi < 2; mi++)
        #pragma unroll
        for (int ni = 0; ni < 4; ni++) {
            int row0 = m0w + mi * 16 + (lane >> 2);
            int col  = n0w + ni * 8 + ((lane & 3) << 1);
            #pragma unroll
            for (int rr = 0; rr < 2; rr++) {
                int row = row0 + rr * 8;
                size_t token = (size_t)bb * S_ + i0 + row;
                size_t o = (token * E_ + hh * 64 + col) >> 1;
                ((__half2*)ctxh)[o] =
                    __floats2half2_rn(ctx[mi][ni][rr * 2 + 0],
                                      ctx[mi][ni][rr * 2 + 1]);
            }
        }
}

// ================= conversions ===========================================
// fp32 -> plain fp16, 4 elems/thread
__global__ __launch_bounds__(256) void conv_h4_kernel(
    const float4* __restrict__ in, __half2* __restrict__ out, int n4)
{
    int i = blockIdx.x * 256 + threadIdx.x;
    if (i < n4) {
        float4 v = in[i];
        out[2 * i]     = __floats2half2_rn(v.x, v.y);
        out[2 * i + 1] = __floats2half2_rn(v.z, v.w);
    }
}

// W[K,N] fp32 -> Wt[N,K] fp16 hi/lo
__global__ __launch_bounds__(256) void transconv_h_kernel(
    const float* __restrict__ W, __half* __restrict__ hi,
    __half* __restrict__ lo, int K, int N)
{
    __shared__ float t[32][33];
    const int k0 = blockIdx.y * 32, n0 = blockIdx.x * 32;
    const int tx = threadIdx.x & 31, ty = threadIdx.x >> 5;
    #pragma unroll
    for (int i = 0; i < 32; i += 8)
        t[ty + i][tx] = W[(size_t)(k0 + ty + i) * N + n0 + tx];
    __syncthreads();
    #pragma unroll
    for (int i = 0; i < 32; i += 8) {
        float x = t[tx][ty + i];
        __half h = __float2half_rn(x);
        size_t o = (size_t)(n0 + ty + i) * K + k0 + tx;
        hi[o] = h;
        lo[o] = __float2half_rn(x - __half2float(h));
    }
}

// [bh][s][d] 16-bit -> [bh][d][s] 16-bit (hi and lo together)
__global__ __launch_bounds__(256) void transpose16_kernel(
    const uint16_t* __restrict__ hi_in, const uint16_t* __restrict__ lo_in,
    uint16_t* __restrict__ hi_out, uint16_t* __restrict__ lo_out)
{
    __shared__ uint16_t th[32][33];
    __shared__ uint16_t tl[32][33];
    const int bh = blockIdx.z;
    const int s0 = blockIdx.x * 32, d0 = blockIdx.y * 32;
    const int tx = threadIdx.x & 31, ty = threadIdx.x >> 5;
    #pragma unroll
    for (int i = 0; i < 32; i += 8) {
        size_t src = ((size_t)bh * S_ + s0 + ty + i) * D_ + d0 + tx;
        th[ty + i][tx] = hi_in[src];
        tl[ty + i][tx] = lo_in[src];
    }
    __syncthreads();
    #pragma unroll
    for (int i = 0; i < 32; i += 8) {
        size_t dst = ((size_t)bh * D_ + d0 + ty + i) * S_ + s0 + tx;
        hi_out[dst] = th[tx][ty + i];
        tl_out:
        lo_out[dst] = tl[tx][ty + i];
    }
}

// ---------------- launch ----------------
extern "C" void kernel_launch(void* const* d_in, const int* in_sizes, int n_in,
                              void* d_out, int out_size)
{
    const float* query = (const float*)d_in[0];
    const float* key   = (const float*)d_in[1];
    const float* value = (const float*)d_in[2];
    const float* Wq    = (const float*)d_in[3];
    const float* bq    = (const float*)d_in[4];
    const float* Wk    = (const float*)d_in[5];
    const float* bk    = (const float*)d_in[6];
    const float* Wv    = (const float*)d_in[7];
    const float* bv    = (const float*)d_in[8];
    const float* Wo    = (const float*)d_in[9];
    const float* bo    = (const float*)d_in[10];

    float* out  = (float*)d_out;                 // [B,S,E]
    float* Wbuf = out + (size_t)M_ * E_;         // [B,H,S,S]

    __half *ahf, *wohi, *wolo, *qhi, *khi, *klo, *vhi, *vlo, *vthi, *vtlo, *ctxh;
    float *gps, *gri;
    cudaGetSymbolAddress((void**)&ahf,  g_Ahf);
    cudaGetSymbolAddress((void**)&wohi, g_Wohi);
    cudaGetSymbolAddress((void**)&wolo, g_Wolo);
    cudaGetSymbolAddress((void**)&qhi,  g_qhi);
    cudaGetSymbolAddress((void**)&khi,  g_khi);
    cudaGetSymbolAddress((void**)&klo,  g_klo);
    cudaGetSymbolAddress((void**)&vhi,  g_vhi);
    cudaGetSymbolAddress((void**)&vlo,  g_vlo);
    cudaGetSymbolAddress((void**)&vthi, g_vthi);
    cudaGetSymbolAddress((void**)&vtlo, g_vtlo);
    cudaGetSymbolAddress((void**)&ctxh, g_ctxh);
    cudaGetSymbolAddress((void**)&gps,  g_psum);
    cudaGetSymbolAddress((void**)&gri,  g_rinv);

    const int SMEM_G = 2 * (128 * 80 + 2 * 128 * 80);  // 61440
    cudaFuncSetAttribute(h2term_gemm<0>,
                         cudaFuncAttributeMaxDynamicSharedMemorySize, SMEM_G);
    cudaFuncSetAttribute(h2term_gemm<1>,
                         cudaFuncAttributeMaxDynamicSharedMemorySize, SMEM_G);
    cudaFuncSetAttribute(h2term_gemm<4>,
                         cudaFuncAttributeMaxDynamicSharedMemorySize, SMEM_G);
    cudaFuncSetAttribute(flash_av_kernel,
                         cudaFuncAttributeMaxDynamicSharedMemorySize, FA_SMEM);

    // ---- projections (fp16 2-term, write head-major fp16 hi/lo) ----
    conv_h4_kernel<<<(M_ * QD_ / 4 + 255) / 256, 256>>>(
        (const float4*)query, (__half2*)ahf, M_ * QD_ / 4);
    transconv_h_kernel<<<dim3(E_ / 32, QD_ / 32), 256>>>(Wq, wohi, wolo, QD_, E_);
    h2term_gemm<1><<<dim3(E_ / 128, M_ / 128, 1), 256, SMEM_G>>>(
        ahf, wohi, wolo, bq, nullptr, qhi, nullptr, nullptr,
        QD_, QD_, QD_, E_, 0, 0, 0, 1.0f);

    conv_h4_kernel<<<(M_ * KD_ / 4 + 255) / 256, 256>>>(
        (const float4*)key, (__half2*)ahf, M_ * KD_ / 4);
    transconv_h_kernel<<<dim3(E_ / 32, KD_ / 32), 256>>>(Wk, wohi, wolo, KD_, E_);
    h2term_gemm<1><<<dim3(E_ / 128, M_ / 128, 1), 256, SMEM_G>>>(
        ahf, wohi, wolo, bk, nullptr, khi, klo, nullptr,
        KD_, KD_, KD_, E_, 0, 0, 0, 1.0f);

    conv_h4_kernel<<<(M_ * VD_ / 4 + 255) / 256, 256>>>(
        (const float4*)value, (__half2*)ahf, M_ * VD_ / 4);
    transconv_h_kernel<<<dim3(E_ / 32, VD_ / 32), 256>>>(Wv, wohi, wolo, VD_, E_);
    h2term_gemm<1><<<dim3(E_ / 128, M_ / 128, 1), 256, SMEM_G>>>(
        ahf, wohi, wolo, bv, nullptr, vhi, vlo, nullptr,
        VD_, VD_, VD_, E_, 0, 0, 0, 1.0f);

    transpose16_kernel<<<dim3(S_ / 32, D_ / 32, BH_), 256>>>(
        (const uint16_t*)vhi, (const uint16_t*)vlo,
        (uint16_t*)vthi, (uint16_t*)vtlo);

    // ---- pass 1: row-sum stats only ----
    h2term_gemm<4><<<dim3(S_ / 128, S_ / 128, BH_), 256, SMEM_G>>>(
        qhi, khi, klo, nullptr, nullptr, nullptr, nullptr, gps,
        D_, D_, D_, S_,
        (long long)S_ * D_, (long long)S_ * D_, 0, 0.125f);

    combine_kernel<<<(BH_ * S_) / 256, 256>>>(gps, gri);

    // ---- pass 2: fused QK recompute + weights write + AV ----
    flash_av_kernel<<<dim3(S_ / 128, BH_), 256, FA_SMEM>>>(
        qhi, khi, klo, vthi, vtlo, gri, Wbuf, ctxh);

    // ---- output projection ----
    transconv_h_kernel<<<dim3(E_ / 32, E_ / 32), 256>>>(Wo, wohi, wolo, E_, E_);
    h2term_gemm<0><<<dim3(E_ / 128, M_ / 128, 1), 256, SMEM_G>>>(
        ctxh, wohi, wolo, bo, out, nullptr, nullptr, nullptr,
        E_, E_, E_, E_, 0, 0, 0, 1.0f);
}

// round 15
// speedup vs baseline: 1.2847x; 1.0599x over previous
#include <cuda_runtime.h>
#include <cuda_fp16.h>
#include <cstdint>

#define B_   4
#define S_   2048
#define E_   1024
#define H_   16
#define D_   64
#define QD_  1024
#define KD_  768
#define VD_  768
#define M_   (B_ * S_)          // 8192
#define BH_  (B_ * H_)          // 64

// ---------------- device scratch (no allocations allowed) ----------------
__device__ __align__(16) __half g_Ahf[M_ * E_];
__device__ __align__(16) __half g_Wohi[E_ * E_];
__device__ __align__(16) __half g_Wolo[E_ * E_];
__device__ __align__(16) __half g_qhi[BH_ * S_ * D_];
__device__ __align__(16) __half g_khi[BH_ * S_ * D_];
__device__ __align__(16) __half g_klo[BH_ * S_ * D_];
__device__ __align__(16) __half g_vhi[BH_ * S_ * D_];
__device__ __align__(16) __half g_vlo[BH_ * S_ * D_];
__device__ __align__(16) __half g_vthi[BH_ * D_ * S_];
__device__ __align__(16) __half g_vtlo[BH_ * D_ * S_];
__device__ __align__(16) __half g_ctxh[M_ * E_];
__device__ float g_psum[BH_ * 16 * S_];
__device__ float g_rinv[BH_ * S_];

// ======================= helpers ============================
__device__ __forceinline__ uint32_t smem_u32(const void* p) {
    uint32_t a;
    asm("{ .reg .u64 t; cvta.to.shared.u64 t, %1; cvt.u32.u64 %0, t; }"
        : "=r"(a) : "l"(p));
    return a;
}
__device__ __forceinline__ void cp16(uint32_t dst, const void* src) {
    asm volatile("cp.async.cg.shared.global [%0], [%1], 16;" :: "r"(dst), "l"(src));
}
#define LDSM4(R, addr) \
    asm volatile("ldmatrix.sync.aligned.m8n8.x4.shared.b16 {%0,%1,%2,%3}, [%4];" \
                 : "=r"((R)[0]), "=r"((R)[1]), "=r"((R)[2]), "=r"((R)[3]) : "r"(addr))
#define MMA_F16(c, a, b0, b1) \
    asm volatile("mma.sync.aligned.m16n8k16.row.col.f32.f16.f16.f32 " \
                 "{%0,%1,%2,%3}, {%4,%5,%6,%7}, {%8,%9}, {%0,%1,%2,%3};" \
                 : "+f"((c)[0]), "+f"((c)[1]), "+f"((c)[2]), "+f"((c)[3]) \
                 : "r"((a)[0]), "r"((a)[1]), "r"((a)[2]), "r"((a)[3]), "r"(b0), "r"(b1))

__device__ __forceinline__ float fast_exp(float x) {
    float t = x * 1.44269504088896341f;
    t = fmaxf(t, -125.0f);
    float r = t + 12582912.0f;
    int   n = __float_as_int(r) - 0x4B400000;
    float f = t - (r - 12582912.0f);
    float p = 1.33336498e-3f;
    p = fmaf(p, f, 9.61011466e-3f);
    p = fmaf(p, f, 5.55036595e-2f);
    p = fmaf(p, f, 2.40226510e-1f);
    p = fmaf(p, f, 6.93147182e-1f);
    p = fmaf(p, f, 1.0f);
    return __int_as_float((n + 127) << 23) * p;
}

// fp32 pair -> fp16 hi/lo pair at half2-element index o (lo optional)
__device__ __forceinline__ void store_hl_h2(
    void* Ohi, void* Olo, size_t o, float x0, float x1)
{
    __half2 hh = __floats2half2_rn(x0, x1);
    ((__half2*)Ohi)[o] = hh;
    if (Olo) {
        float l0 = x0 - __half2float(__low2half(hh));
        float l1 = x1 - __half2float(__high2half(hh));
        ((__half2*)Olo)[o] = __floats2half2_rn(l0, l1);
    }
}

// ================= fp16 split tensor-core GEMM ===========================
// TERMS=2: C = A·Bh + A·Bl ; TERMS=1: C = A·Bh (Bl ignored/not loaded).
// A: [M,K] fp16, B: [N,K] fp16 (hi[, lo]).  Tiles 128x128, BK=32, 2-stage.
// EPI 0: fp32 C (+bias, alpha)
// EPI 1: fp16 hi/lo head-major [bh][s][d] (+bias); Olo optional
// EPI 4: stats only — per-(row,colblock) sums of exp(alpha*acc) to gps, no C
template<int EPI, int TERMS>
__global__ __launch_bounds__(256) void h2term_gemm(
    const __half* __restrict__ A_, const __half* __restrict__ Bhi_,
    const __half* __restrict__ Blo_,
    const float* __restrict__ bias, float* __restrict__ C,
    void* __restrict__ Ohi, void* __restrict__ Olo,
    float* __restrict__ gps,
    int K, int ldA, int ldB, int ldC,
    long long strideA, long long strideB, long long sCo, float alpha)
{
    constexpr int SSA = 128 * 80;
    constexpr int BOF = 128 * 80;
    constexpr int SS  = SSA + TERMS * BOF;
    extern __shared__ __align__(16) char smem[];
    const uint32_t sbase = smem_u32(smem);

    const int tid  = threadIdx.x;
    const int lane = tid & 31;
    const int wid  = tid >> 5;
    const int m0w  = (wid >> 1) * 32;
    const int n0w  = (wid & 1) * 64;
    const int m0   = blockIdx.y * 128;
    const int n0   = blockIdx.x * 128;
    const size_t z = blockIdx.z;

    const uint16_t* Ah16 = (const uint16_t*)A_ + z * strideA + (size_t)m0 * ldA;
    const uint16_t* Bh = (const uint16_t*)Bhi_ + z * strideB + (size_t)n0 * ldB;
    const uint16_t* Bl = (TERMS == 2)
        ? (const uint16_t*)Blo_ + z * strideB + (size_t)n0 * ldB : nullptr;

    const int T = K / 32;
    float acc[2][8][4];
    #pragma unroll
    for (int i = 0; i < 2; i++)
        #pragma unroll
        for (int j = 0; j < 8; j++)
            #pragma unroll
            for (int q = 0; q < 4; q++) acc[i][j][q] = 0.0f;

    auto load_stage = [&](int it) {
        const uint32_t sb = sbase + (it & 1) * SS;
        const int k0 = it * 32;
        #pragma unroll
        for (int c = tid; c < TERMS * 512; c += 256) {
            int tile = (c >= 512) ? 1 : 0;
            int cc   = c - tile * 512;
            int r    = cc >> 2, seg = cc & 3;
            const uint16_t* src = (tile ? Bl : Bh) + (size_t)r * ldB + k0 + seg * 8;
            cp16(sb + SSA + tile * BOF + r * 80 + seg * 16, src);
        }
        #pragma unroll
        for (int c = tid; c < 512; c += 256) {
            int r = c >> 2, seg = c & 3;
            cp16(sb + r * 80 + seg * 16, Ah16 + (size_t)r * ldA + k0 + seg * 8);
        }
    };

    auto do_mmas = [&](int it) {
        const uint32_t sA = sbase + (it & 1) * SS;
        const uint32_t sB = sA + SSA;
        #pragma unroll
        for (int kk = 0; kk < 2; kk++) {
            uint32_t ah[2][4];
            #pragma unroll
            for (int mi = 0; mi < 2; mi++) {
                uint32_t addr = sA + ((m0w + mi * 16 + (lane & 15)) * 40
                                      + kk * 16 + ((lane >> 4) << 3)) * 2;
                LDSM4(ah[mi], addr);
            }
            uint32_t bh[8][2], bl[8][2];
            #pragma unroll
            for (int nj = 0; nj < 4; nj++) {
                uint32_t row = n0w + nj * 16 + (lane & 7) + ((lane >> 4) << 3);
                uint32_t col = kk * 16 + (((lane >> 3) & 1) << 3);
                uint32_t addr = sB + (row * 40 + col) * 2;
                uint32_t t4[4];
                LDSM4(t4, addr);
                bh[2 * nj][0] = t4[0]; bh[2 * nj][1] = t4[1];
                bh[2 * nj + 1][0] = t4[2]; bh[2 * nj + 1][1] = t4[3];
                if (TERMS == 2) {
                    LDSM4(t4, addr + BOF);
                    bl[2 * nj][0] = t4[0]; bl[2 * nj][1] = t4[1];
                    bl[2 * nj + 1][0] = t4[2]; bl[2 * nj + 1][1] = t4[3];
                }
            }
            #pragma unroll
            for (int mi = 0; mi < 2; mi++)
                #pragma unroll
                for (int ni = 0; ni < 8; ni++) {
                    MMA_F16(acc[mi][ni], ah[mi], bh[ni][0], bh[ni][1]);
                    if (TERMS == 2)
                        MMA_F16(acc[mi][ni], ah[mi], bl[ni][0], bl[ni][1]);
                }
        }
    };

    load_stage(0);
    asm volatile("cp.async.commit_group;" ::: "memory");
    for (int it = 0; it < T; it++) {
        if (it + 1 < T) {
            load_stage(it + 1);
            asm volatile("cp.async.commit_group;" ::: "memory");
            asm volatile("cp.async.wait_group 1;" ::: "memory");
        } else {
            asm volatile("cp.async.wait_group 0;" ::: "memory");
        }
        __syncthreads();
        do_mmas(it);
        __syncthreads();
    }

    // ---------------- epilogue ----------------
    if (EPI == 0) {
        #pragma unroll
        for (int mi = 0; mi < 2; mi++)
            #pragma unroll
            for (int ni = 0; ni < 8; ni++) {
                int row = m0 + m0w + mi * 16 + (lane >> 2);
                int col = n0 + n0w + ni * 8 + ((lane & 3) << 1);
                float b0 = bias ? __ldg(bias + col) : 0.0f;
                float b1 = bias ? __ldg(bias + col + 1) : 0.0f;
                C[(size_t)row * ldC + col]           = acc[mi][ni][0] * alpha + b0;
                C[(size_t)row * ldC + col + 1]       = acc[mi][ni][1] * alpha + b1;
                C[(size_t)(row + 8) * ldC + col]     = acc[mi][ni][2] * alpha + b0;
                C[(size_t)(row + 8) * ldC + col + 1] = acc[mi][ni][3] * alpha + b1;
            }
    } else if (EPI == 1) {
        #pragma unroll
        for (int mi = 0; mi < 2; mi++)
            #pragma unroll
            for (int ni = 0; ni < 8; ni++) {
                int row = m0 + m0w + mi * 16 + (lane >> 2);
                int col = n0 + n0w + ni * 8 + ((lane & 3) << 1);
                float b0 = bias ? __ldg(bias + col) : 0.0f;
                float b1 = bias ? __ldg(bias + col + 1) : 0.0f;
                int h = col >> 6, d = col & 63;
                #pragma unroll
                for (int rr = 0; rr < 2; rr++) {
                    int r = row + rr * 8;
                    int b = r >> 11, s = r & 2047;
                    size_t o = ((((size_t)(b * 16 + h)) * S_ + s) * D_ + d) >> 1;
                    store_hl_h2(Ohi, Olo, o,
                                acc[mi][ni][rr * 2 + 0] + b0,
                                acc[mi][ni][rr * 2 + 1] + b1);
                }
            }
    } else {
        // EPI == 4: row-sum partials of exp(alpha*acc); no C write
        __shared__ float ps_s[128][2];
        float rs[2][2] = {{0.0f, 0.0f}, {0.0f, 0.0f}};
        #pragma unroll
        for (int mi = 0; mi < 2; mi++)
            #pragma unroll
            for (int ni = 0; ni < 8; ni++) {
                rs[mi][0] += fast_exp(acc[mi][ni][0] * alpha)
                           + fast_exp(acc[mi][ni][1] * alpha);
                rs[mi][1] += fast_exp(acc[mi][ni][2] * alpha)
                           + fast_exp(acc[mi][ni][3] * alpha);
            }
        #pragma unroll
        for (int mi = 0; mi < 2; mi++)
            #pragma unroll
            for (int rr = 0; rr < 2; rr++) {
                float v = rs[mi][rr];
                v += __shfl_xor_sync(0xFFFFFFFFu, v, 1);
                v += __shfl_xor_sync(0xFFFFFFFFu, v, 2);
                rs[mi][rr] = v;
            }
        if ((lane & 3) == 0) {
            #pragma unroll
            for (int mi = 0; mi < 2; mi++)
                #pragma unroll
                for (int rr = 0; rr < 2; rr++)
                    ps_s[m0w + mi * 16 + (lane >> 2) + rr * 8][wid & 1] = rs[mi][rr];
        }
        __syncthreads();
        if (tid < 128) {
            size_t o = ((size_t)z * gridDim.x + blockIdx.x) * (size_t)S_ + m0 + tid;
            gps[o] = ps_s[tid][0] + ps_s[tid][1];
        }
    }
}

// ---------------- combine: rinv = 1 / sum of 16 col-block partials -------
__global__ __launch_bounds__(256) void combine_kernel(
    const float* __restrict__ gps, float* __restrict__ rinv)
{
    int g = blockIdx.x * 256 + threadIdx.x;
    int bh = g >> 11, r = g & 2047;
    const float* ps = gps + (size_t)bh * 16 * S_ + r;
    float s = 0.0f;
    #pragma unroll
    for (int jb = 0; jb < 16; jb++) s += ps[(size_t)jb * S_];
    rinv[g] = 1.0f / s;
}

// ================= flash attention: QK recompute + P write + AV ==========
#define FA_Q0   0
#define FA_K0   20480
#define FA_V0   61440
#define FA_P0   102400
#define FA_SMEM 122880
__global__ __launch_bounds__(256) void flash_av_kernel(
    const __half* __restrict__ qh,
    const __half* __restrict__ khi, const __half* __restrict__ klo,
    const __half* __restrict__ vthi, const __half* __restrict__ vtlo,
    const float* __restrict__ rinv, float* __restrict__ Wbuf,
    __half* __restrict__ ctxh)
{
    extern __shared__ __align__(16) char smem[];
    const uint32_t sbase = smem_u32(smem);
    __shared__ float s_r[128];

    const int tid  = threadIdx.x;
    const int lane = tid & 31;
    const int wid  = tid >> 5;
    const int m0w  = (wid >> 1) * 32;
    const int n0w  = (wid & 1) * 32;
    const int i0   = blockIdx.x * 128;
    const int bh   = blockIdx.y;
    const int bb   = bh >> 4, hh = bh & 15;

    if (tid < 128) s_r[tid] = rinv[(size_t)bh * S_ + i0 + tid];

    const __half* qg = qh + ((size_t)bh * S_ + i0) * D_;
    #pragma unroll
    for (int l = 0; l < 4; l++) {
        int c = tid + l * 256;
        int it = c >> 9, cc = c & 511, r = cc >> 2, seg = cc & 3;
        cp16(sbase + FA_Q0 + it * 10240 + r * 80 + seg * 16,
             qg + (size_t)r * D_ + it * 32 + seg * 8);
    }
    auto load_kv = [&](int j) {
        const int st = j & 1, j0 = j * 64;
        #pragma unroll
        for (int l = 0; l < 4; l++) {
            int c = tid + l * 256;
            int t = c >> 9, cc = c & 511;
            int r = cc >> 3, rem = cc & 7, ch = rem >> 2, seg = rem & 3;
            const __half* src = (t ? klo : khi)
                + ((size_t)bh * S_ + j0 + r) * D_ + ch * 32 + seg * 8;
            cp16(sbase + FA_K0 + st * 20480 + t * 10240 + ch * 5120
                 + r * 80 + seg * 16, src);
        }
        #pragma unroll
        for (int l = 0; l < 4; l++) {
            int c = tid + l * 256;
            int t = c >> 9, cc = c & 511;
            int r = cc >> 3, rem = cc & 7, ch = rem >> 2, seg = rem & 3;
            const __half* src = (t ? vtlo : vthi)
                + ((size_t)bh * D_ + r) * S_ + j0 + ch * 32 + seg * 8;
            cp16(sbase + FA_V0 + st * 20480 + t * 10240 + ch * 5120
                 + r * 80 + seg * 16, src);
        }
    };
    load_kv(0);
    asm volatile("cp.async.commit_group;" ::: "memory");

    float ctx[2][4][4];
    #pragma unroll
    for (int a = 0; a < 2; a++)
        #pragma unroll
        for (int b = 0; b < 4; b++)
            #pragma unroll
            for (int q = 0; q < 4; q++) ctx[a][b][q] = 0.0f;

    for (int j = 0; j < 32; j++) {
        const int st = j & 1, j0 = j * 64;
        if (j + 1 < 32) {
            load_kv(j + 1);
            asm volatile("cp.async.commit_group;" ::: "memory");
            asm volatile("cp.async.wait_group 1;" ::: "memory");
        } else {
            asm volatile("cp.async.wait_group 0;" ::: "memory");
        }
        __syncthreads();

        float accs[2][4][4];
        #pragma unroll
        for (int a = 0; a < 2; a++)
            #pragma unroll
            for (int b = 0; b < 4; b++)
                #pragma unroll
                for (int q = 0; q < 4; q++) accs[a][b][q] = 0.0f;
        #pragma unroll
        for (int it = 0; it < 2; it++) {
            #pragma unroll
            for (int kk = 0; kk < 2; kk++) {
                uint32_t ah[2][4];
                #pragma unroll
                for (int mi = 0; mi < 2; mi++) {
                    uint32_t addr = sbase + FA_Q0 + it * 10240
                        + ((m0w + mi * 16 + (lane & 15)) * 40
                           + kk * 16 + ((lane >> 4) << 3)) * 2;
                    LDSM4(ah[mi], addr);
                }
                uint32_t bhf[4][2], blf[4][2];
                #pragma unroll
                for (int nj = 0; nj < 2; nj++) {
                    uint32_t row = n0w + nj * 16 + (lane & 7) + ((lane >> 4) << 3);
                    uint32_t col = kk * 16 + (((lane >> 3) & 1) << 3);
                    uint32_t addr = sbase + FA_K0 + st * 20480 + it * 5120
                        + (row * 40 + col) * 2;
                    uint32_t t4[4];
                    LDSM4(t4, addr);
                    bhf[2 * nj][0] = t4[0]; bhf[2 * nj][1] = t4[1];
                    bhf[2 * nj + 1][0] = t4[2]; bhf[2 * nj + 1][1] = t4[3];
                    LDSM4(t4, addr + 10240);
                    blf[2 * nj][0] = t4[0]; blf[2 * nj][1] = t4[1];
                    blf[2 * nj + 1][0] = t4[2]; blf[2 * nj + 1][1] = t4[3];
                }
                #pragma unroll
                for (int mi = 0; mi < 2; mi++)
                    #pragma unroll
                    for (int ni = 0; ni < 4; ni++) {
                        MMA_F16(accs[mi][ni], ah[mi], bhf[ni][0], bhf[ni][1]);
                        MMA_F16(accs[mi][ni], ah[mi], blf[ni][0], blf[ni][1]);
                    }
            }
        }

        #pragma unroll
        for (int mi = 0; mi < 2; mi++)
            #pragma unroll
            for (int ni = 0; ni < 4; ni++) {
                int row0 = m0w + mi * 16 + (lane >> 2);
                int col  = n0w + ni * 8 + ((lane & 3) << 1);
                #pragma unroll
                for (int rr = 0; rr < 2; rr++) {
                    int row = row0 + rr * 8;
                    float p0 = fast_exp(accs[mi][ni][rr * 2 + 0] * 0.125f) * s_r[row];
                    float p1 = fast_exp(accs[mi][ni][rr * 2 + 1] * 0.125f) * s_r[row];
                    float2 w2; w2.x = p0; w2.y = p1;
                    *(float2*)(Wbuf + ((size_t)bh * S_ + i0 + row) * S_ + j0 + col) = w2;
                    __half2 hp = __floats2half2_rn(p0, p1);
                    int ch = col >> 5, c32 = col & 31;
                    *(uint32_t*)(smem + FA_P0 + ch * 10240 + row * 80 + c32 * 2)
                        = *(uint32_t*)&hp;
                }
            }
        __syncthreads();

        #pragma unroll
        for (int it = 0; it < 2; it++) {
            #pragma unroll
            for (int kk = 0; kk < 2; kk++) {
                uint32_t ah[2][4];
                #pragma unroll
                for (int mi = 0; mi < 2; mi++) {
                    uint32_t addr = sbase + FA_P0 + it * 10240
                        + ((m0w + mi * 16 + (lane & 15)) * 40
                           + kk * 16 + ((lane >> 4) << 3)) * 2;
                    LDSM4(ah[mi], addr);
                }
                uint32_t bhf[4][2], blf[4][2];
                #pragma unroll
                for (int nj = 0; nj < 2; nj++) {
                    uint32_t row = n0w + nj * 16 + (lane & 7) + ((lane >> 4) << 3);
                    uint32_t col = kk * 16 + (((lane >> 3) & 1) << 3);
                    uint32_t addr = sbase + FA_V0 + st * 20480 + it * 5120
                        + (row * 40 + col) * 2;
                    uint32_t t4[4];
                    LDSM4(t4, addr);
                    bhf[2 * nj][0] = t4[0]; bhf[2 * nj][1] = t4[1];
                    bhf[2 * nj + 1][0] = t4[2]; bhf[2 * nj + 1][1] = t4[3];
                    LDSM4(t4, addr + 10240);
                    blf[2 * nj][0] = t4[0]; blf[2 * nj][1] = t4[1];
                    blf[2 * nj + 1][0] = t4[2]; blf[2 * nj + 1][1] = t4[3];
                }
                #pragma unroll
                for (int mi = 0; mi < 2; mi++)
                    #pragma unroll
                    for (int ni = 0; ni < 4; ni++) {
                        MMA_F16(ctx[mi][ni], ah[mi], bhf[ni][0], bhf[ni][1]);
                        MMA_F16(ctx[mi][ni], ah[mi], blf[ni][0], blf[ni][1]);
                    }
            }
        }
    }

    #pragma unroll
    for (int mi = 0; mi < 2; mi++)
        #pragma unroll
        for (int ni = 0; ni < 4; ni++) {
            int row0 = m0w + mi * 16 + (lane >> 2);
            int col  = n0w + ni * 8 + ((lane & 3) << 1);
            #pragma unroll
            for (int rr = 0; rr < 2; rr++) {
                int row = row0 + rr * 8;
                size_t token = (size_t)bb * S_ + i0 + row;
                size_t o = (token * E_ + hh * 64 + col) >> 1;
                ((__half2*)ctxh)[o] =
                    __floats2half2_rn(ctx[mi][ni][rr * 2 + 0],
                                      ctx[mi][ni][rr * 2 + 1]);
            }
        }
}

// ================= conversions ===========================================
__global__ __launch_bounds__(256) void conv_h4_kernel(
    const float4* __restrict__ in, __half2* __restrict__ out, int n4)
{
    int i = blockIdx.x * 256 + threadIdx.x;
    if (i < n4) {
        float4 v = in[i];
        out[2 * i]     = __floats2half2_rn(v.x, v.y);
        out[2 * i + 1] = __floats2half2_rn(v.z, v.w);
    }
}

// W[K,N] fp32 -> Wt[N,K] fp16 hi/lo
__global__ __launch_bounds__(256) void transconv_h_kernel(
    const float* __restrict__ W, __half* __restrict__ hi,
    __half* __restrict__ lo, int K, int N)
{
    __shared__ float t[32][33];
    const int k0 = blockIdx.y * 32, n0 = blockIdx.x * 32;
    const int tx = threadIdx.x & 31, ty = threadIdx.x >> 5;
    #pragma unroll
    for (int i = 0; i < 32; i += 8)
        t[ty + i][tx] = W[(size_t)(k0 + ty + i) * N + n0 + tx];
    __syncthreads();
    #pragma unroll
    for (int i = 0; i < 32; i += 8) {
        float x = t[tx][ty + i];
        __half h = __float2half_rn(x);
        size_t o = (size_t)(n0 + ty + i) * K + k0 + tx;
        hi[o] = h;
        lo[o] = __float2half_rn(x - __half2float(h));
    }
}

// [bh][s][d] 16-bit -> [bh][d][s] 16-bit (hi and lo together)
__global__ __launch_bounds__(256) void transpose16_kernel(
    const uint16_t* __restrict__ hi_in, const uint16_t* __restrict__ lo_in,
    uint16_t* __restrict__ hi_out, uint16_t* __restrict__ lo_out)
{
    __shared__ uint16_t th[32][33];
    __shared__ uint16_t tl[32][33];
    const int bh = blockIdx.z;
    const int s0 = blockIdx.x * 32, d0 = blockIdx.y * 32;
    const int tx = threadIdx.x & 31, ty = threadIdx.x >> 5;
    #pragma unroll
    for (int i = 0; i < 32; i += 8) {
        size_t src = ((size_t)bh * S_ + s0 + ty + i) * D_ + d0 + tx;
        th[ty + i][tx] = hi_in[src];
        tl[ty + i][tx] = lo_in[src];
    }
    __syncthreads();
    #pragma unroll
    for (int i = 0; i < 32; i += 8) {
        size_t dst = ((size_t)bh * D_ + d0 + ty + i) * S_ + s0 + tx;
        hi_out[dst] = th[tx][ty + i];
        lo_out[dst] = tl[tx][ty + i];
    }
}

// ---------------- launch ----------------
extern "C" void kernel_launch(void* const* d_in, const int* in_sizes, int n_in,
                              void* d_out, int out_size)
{
    const float* query = (const float*)d_in[0];
    const float* key   = (const float*)d_in[1];
    const float* value = (const float*)d_in[2];
    const float* Wq    = (const float*)d_in[3];
    const float* bq    = (const float*)d_in[4];
    const float* Wk    = (const float*)d_in[5];
    const float* bk    = (const float*)d_in[6];
    const float* Wv    = (const float*)d_in[7];
    const float* bv    = (const float*)d_in[8];
    const float* Wo    = (const float*)d_in[9];
    const float* bo    = (const float*)d_in[10];

    float* out  = (float*)d_out;                 // [B,S,E]
    float* Wbuf = out + (size_t)M_ * E_;         // [B,H,S,S]

    __half *ahf, *wohi, *wolo, *qhi, *khi, *klo, *vhi, *vlo, *vthi, *vtlo, *ctxh;
    float *gps, *gri;
    cudaGetSymbolAddress((void**)&ahf,  g_Ahf);
    cudaGetSymbolAddress((void**)&wohi, g_Wohi);
    cudaGetSymbolAddress((void**)&wolo, g_Wolo);
    cudaGetSymbolAddress((void**)&qhi,  g_qhi);
    cudaGetSymbolAddress((void**)&khi,  g_khi);
    cudaGetSymbolAddress((void**)&klo,  g_klo);
    cudaGetSymbolAddress((void**)&vhi,  g_vhi);
    cudaGetSymbolAddress((void**)&vlo,  g_vlo);
    cudaGetSymbolAddress((void**)&vthi, g_vthi);
    cudaGetSymbolAddress((void**)&vtlo, g_vtlo);
    cudaGetSymbolAddress((void**)&ctxh, g_ctxh);
    cudaGetSymbolAddress((void**)&gps,  g_psum);
    cudaGetSymbolAddress((void**)&gri,  g_rinv);

    const int SMEM_G2 = 2 * (128 * 80 + 2 * 128 * 80);  // 61440 (2-term)
    const int SMEM_G1 = 2 * (128 * 80 + 1 * 128 * 80);  // 40960 (1-term stats)
    cudaFuncSetAttribute(h2term_gemm<0, 2>,
                         cudaFuncAttributeMaxDynamicSharedMemorySize, SMEM_G2);
    cudaFuncSetAttribute(h2term_gemm<1, 2>,
                         cudaFuncAttributeMaxDynamicSharedMemorySize, SMEM_G2);
    cudaFuncSetAttribute(h2term_gemm<4, 1>,
                         cudaFuncAttributeMaxDynamicSharedMemorySize, SMEM_G1);
    cudaFuncSetAttribute(flash_av_kernel,
                         cudaFuncAttributeMaxDynamicSharedMemorySize, FA_SMEM);

    // ---- projections (fp16 2-term, write head-major fp16 hi/lo) ----
    conv_h4_kernel<<<(M_ * QD_ / 4 + 255) / 256, 256>>>(
        (const float4*)query, (__half2*)ahf, M_ * QD_ / 4);
    transconv_h_kernel<<<dim3(E_ / 32, QD_ / 32), 256>>>(Wq, wohi, wolo, QD_, E_);
    h2term_gemm<1, 2><<<dim3(E_ / 128, M_ / 128, 1), 256, SMEM_G2>>>(
        ahf, wohi, wolo, bq, nullptr, qhi, nullptr, nullptr,
        QD_, QD_, QD_, E_, 0, 0, 0, 1.0f);

    conv_h4_kernel<<<(M_ * KD_ / 4 + 255) / 256, 256>>>(
        (const float4*)key, (__half2*)ahf, M_ * KD_ / 4);
    transconv_h_kernel<<<dim3(E_ / 32, KD_ / 32), 256>>>(Wk, wohi, wolo, KD_, E_);
    h2term_gemm<1, 2><<<dim3(E_ / 128, M_ / 128, 1), 256, SMEM_G2>>>(
        ahf, wohi, wolo, bk, nullptr, khi, klo, nullptr,
        KD_, KD_, KD_, E_, 0, 0, 0, 1.0f);

    conv_h4_kernel<<<(M_ * VD_ / 4 + 255) / 256, 256>>>(
        (const float4*)value, (__half2*)ahf, M_ * VD_ / 4);
    transconv_h_kernel<<<dim3(E_ / 32, VD_ / 32), 256>>>(Wv, wohi, wolo, VD_, E_);
    h2term_gemm<1, 2><<<dim3(E_ / 128, M_ / 128, 1), 256, SMEM_G2>>>(
        ahf, wohi, wolo, bv, nullptr, vhi, vlo, nullptr,
        VD_, VD_, VD_, E_, 0, 0, 0, 1.0f);

    transpose16_kernel<<<dim3(S_ / 32, D_ / 32, BH_), 256>>>(
        (const uint16_t*)vhi, (const uint16_t*)vlo,
        (uint16_t*)vthi, (uint16_t*)vtlo);

    // ---- pass 1: row-sum stats only (1-term K; rinv err ~4e-5) ----
    h2term_gemm<4, 1><<<dim3(S_ / 128, S_ / 128, BH_), 256, SMEM_G1>>>(
        qhi, khi, nullptr, nullptr, nullptr, nullptr, nullptr, gps,
        D_, D_, D_, S_,
        (long long)S_ * D_, (long long)S_ * D_, 0, 0.125f);

    combine_kernel<<<(BH_ * S_) / 256, 256>>>(gps, gri);

    // ---- pass 2: fused QK recompute + weights write + AV ----
    flash_av_kernel<<<dim3(S_ / 128, BH_), 256, FA_SMEM>>>(
        qhi, khi, klo, vthi, vtlo, gri, Wbuf, ctxh);

    // ---- output projection ----
    transconv_h_kernel<<<dim3(E_ / 32, E_ / 32), 256>>>(Wo, wohi, wolo, E_, E_);
    h2term_gemm<0, 2><<<dim3(E_ / 128, M_ / 128, 1), 256, SMEM_G2>>>(
        ctxh, wohi, wolo, bo, out, nullptr, nullptr, nullptr,
        E_, E_, E_, E_, 0, 0, 0, 1.0f);
}

// round 17
// speedup vs baseline: 1.5085x; 1.1742x over previous
#include <cuda_runtime.h>
#include <cuda_fp16.h>
#include <cstdint>

#define B_   4
#define S_   2048
#define E_   1024
#define H_   16
#define D_   64
#define QD_  1024
#define KD_  768
#define VD_  768
#define M_   (B_ * S_)          // 8192
#define BH_  (B_ * H_)          // 64

// ---------------- device scratch (no allocations allowed) ----------------
__device__ __align__(16) __half g_Ahf[M_ * E_];
__device__ __align__(16) __half g_Wohi[E_ * E_];
__device__ __align__(16) __half g_Wolo[E_ * E_];
__device__ __align__(16) __half g_qhi[BH_ * S_ * D_];
__device__ __align__(16) __half g_khi[BH_ * S_ * D_];
__device__ __align__(16) __half g_klo[BH_ * S_ * D_];
__device__ __align__(16) __half g_vhi[BH_ * S_ * D_];
__device__ __align__(16) __half g_vthi[BH_ * D_ * S_];
__device__ __align__(16) __half g_ctxh[M_ * E_];
__device__ float g_psum[BH_ * 16 * S_];
__device__ float g_rinv[BH_ * S_];

// ======================= helpers ============================
__device__ __forceinline__ uint32_t smem_u32(const void* p) {
    uint32_t a;
    asm("{ .reg .u64 t; cvta.to.shared.u64 t, %1; cvt.u32.u64 %0, t; }"
        : "=r"(a) : "l"(p));
    return a;
}
__device__ __forceinline__ void cp16(uint32_t dst, const void* src) {
    asm volatile("cp.async.cg.shared.global [%0], [%1], 16;" :: "r"(dst), "l"(src));
}
#define LDSM4(R, addr) \
    asm volatile("ldmatrix.sync.aligned.m8n8.x4.shared.b16 {%0,%1,%2,%3}, [%4];" \
                 : "=r"((R)[0]), "=r"((R)[1]), "=r"((R)[2]), "=r"((R)[3]) : "r"(addr))
#define MMA_F16(c, a, b0, b1) \
    asm volatile("mma.sync.aligned.m16n8k16.row.col.f32.f16.f16.f32 " \
                 "{%0,%1,%2,%3}, {%4,%5,%6,%7}, {%8,%9}, {%0,%1,%2,%3};" \
                 : "+f"((c)[0]), "+f"((c)[1]), "+f"((c)[2]), "+f"((c)[3]) \
                 : "r"((a)[0]), "r"((a)[1]), "r"((a)[2]), "r"((a)[3]), "r"(b0), "r"(b1))

__device__ __forceinline__ float fast_exp(float x) {
    float t = x * 1.44269504088896341f;
    t = fmaxf(t, -125.0f);
    float r = t + 12582912.0f;
    int   n = __float_as_int(r) - 0x4B400000;
    float f = t - (r - 12582912.0f);
    float p = 1.33336498e-3f;
    p = fmaf(p, f, 9.61011466e-3f);
    p = fmaf(p, f, 5.55036595e-2f);
    p = fmaf(p, f, 2.40226510e-1f);
    p = fmaf(p, f, 6.93147182e-1f);
    p = fmaf(p, f, 1.0f);
    return __int_as_float((n + 127) << 23) * p;
}

// fp32 pair -> fp16 hi/lo pair at half2-element index o (lo optional)
__device__ __forceinline__ void store_hl_h2(
    void* Ohi, void* Olo, size_t o, float x0, float x1)
{
    __half2 hh = __floats2half2_rn(x0, x1);
    ((__half2*)Ohi)[o] = hh;
    if (Olo) {
        float l0 = x0 - __half2float(__low2half(hh));
        float l1 = x1 - __half2float(__high2half(hh));
        ((__half2*)Olo)[o] = __floats2half2_rn(l0, l1);
    }
}

// ================= fp16 split tensor-core GEMM ===========================
// TERMS=2: C = A·Bh + A·Bl ; TERMS=1: C = A·Bh.
// A: [M,K] fp16, B: [N,K] fp16 (hi[, lo]).  Tiles 128x128, BK=32, 2-stage.
// EPI 0: fp32 C (+bias, alpha)
// EPI 1: fp16 hi/lo head-major [bh][s][d] (+bias); Olo optional
// EPI 4: stats only — per-(row,colblock) sums of exp(alpha*acc) to gps, no C
template<int EPI, int TERMS>
__global__ __launch_bounds__(256) void h2term_gemm(
    const __half* __restrict__ A_, const __half* __restrict__ Bhi_,
    const __half* __restrict__ Blo_,
    const float* __restrict__ bias, float* __restrict__ C,
    void* __restrict__ Ohi, void* __restrict__ Olo,
    float* __restrict__ gps,
    int K, int ldA, int ldB, int ldC,
    long long strideA, long long strideB, long long sCo, float alpha)
{
    constexpr int SSA = 128 * 80;
    constexpr int BOF = 128 * 80;
    constexpr int SS  = SSA + TERMS * BOF;
    extern __shared__ __align__(16) char smem[];
    const uint32_t sbase = smem_u32(smem);

    const int tid  = threadIdx.x;
    const int lane = tid & 31;
    const int wid  = tid >> 5;
    const int m0w  = (wid >> 1) * 32;
    const int n0w  = (wid & 1) * 64;
    const int m0   = blockIdx.y * 128;
    const int n0   = blockIdx.x * 128;
    const size_t z = blockIdx.z;

    const uint16_t* Ah16 = (const uint16_t*)A_ + z * strideA + (size_t)m0 * ldA;
    const uint16_t* Bh = (const uint16_t*)Bhi_ + z * strideB + (size_t)n0 * ldB;
    const uint16_t* Bl = (TERMS == 2)
        ? (const uint16_t*)Blo_ + z * strideB + (size_t)n0 * ldB : nullptr;

    const int T = K / 32;
    float acc[2][8][4];
    #pragma unroll
    for (int i = 0; i < 2; i++)
        #pragma unroll
        for (int j = 0; j < 8; j++)
            #pragma unroll
            for (int q = 0; q < 4; q++) acc[i][j][q] = 0.0f;

    auto load_stage = [&](int it) {
        const uint32_t sb = sbase + (it & 1) * SS;
        const int k0 = it * 32;
        #pragma unroll
        for (int c = tid; c < TERMS * 512; c += 256) {
            int tile = (c >= 512) ? 1 : 0;
            int cc   = c - tile * 512;
            int r    = cc >> 2, seg = cc & 3;
            const uint16_t* src = (tile ? Bl : Bh) + (size_t)r * ldB + k0 + seg * 8;
            cp16(sb + SSA + tile * BOF + r * 80 + seg * 16, src);
        }
        #pragma unroll
        for (int c = tid; c < 512; c += 256) {
            int r = c >> 2, seg = c & 3;
            cp16(sb + r * 80 + seg * 16, Ah16 + (size_t)r * ldA + k0 + seg * 8);
        }
    };

    auto do_mmas = [&](int it) {
        const uint32_t sA = sbase + (it & 1) * SS;
        const uint32_t sB = sA + SSA;
        #pragma unroll
        for (int kk = 0; kk < 2; kk++) {
            uint32_t ah[2][4];
            #pragma unroll
            for (int mi = 0; mi < 2; mi++) {
                uint32_t addr = sA + ((m0w + mi * 16 + (lane & 15)) * 40
                                      + kk * 16 + ((lane >> 4) << 3)) * 2;
                LDSM4(ah[mi], addr);
            }
            uint32_t bh[8][2], bl[8][2];
            #pragma unroll
            for (int nj = 0; nj < 4; nj++) {
                uint32_t row = n0w + nj * 16 + (lane & 7) + ((lane >> 4) << 3);
                uint32_t col = kk * 16 + (((lane >> 3) & 1) << 3);
                uint32_t addr = sB + (row * 40 + col) * 2;
                uint32_t t4[4];
                LDSM4(t4, addr);
                bh[2 * nj][0] = t4[0]; bh[2 * nj][1] = t4[1];
                bh[2 * nj + 1][0] = t4[2]; bh[2 * nj + 1][1] = t4[3];
                if (TERMS == 2) {
                    LDSM4(t4, addr + BOF);
                    bl[2 * nj][0] = t4[0]; bl[2 * nj][1] = t4[1];
                    bl[2 * nj + 1][0] = t4[2]; bl[2 * nj + 1][1] = t4[3];
                }
            }
            #pragma unroll
            for (int mi = 0; mi < 2; mi++)
                #pragma unroll
                for (int ni = 0; ni < 8; ni++) {
                    MMA_F16(acc[mi][ni], ah[mi], bh[ni][0], bh[ni][1]);
                    if (TERMS == 2)
                        MMA_F16(acc[mi][ni], ah[mi], bl[ni][0], bl[ni][1]);
                }
        }
    };

    load_stage(0);
    asm volatile("cp.async.commit_group;" ::: "memory");
    for (int it = 0; it < T; it++) {
        if (it + 1 < T) {
            load_stage(it + 1);
            asm volatile("cp.async.commit_group;" ::: "memory");
            asm volatile("cp.async.wait_group 1;" ::: "memory");
        } else {
            asm volatile("cp.async.wait_group 0;" ::: "memory");
        }
        __syncthreads();
        do_mmas(it);
        __syncthreads();
    }

    // ---------------- epilogue ----------------
    if (EPI == 0) {
        #pragma unroll
        for (int mi = 0; mi < 2; mi++)
            #pragma unroll
            for (int ni = 0; ni < 8; ni++) {
                int row = m0 + m0w + mi * 16 + (lane >> 2);
                int col = n0 + n0w + ni * 8 + ((lane & 3) << 1);
                float b0 = bias ? __ldg(bias + col) : 0.0f;
                float b1 = bias ? __ldg(bias + col + 1) : 0.0f;
                C[(size_t)row * ldC + col]           = acc[mi][ni][0] * alpha + b0;
                C[(size_t)row * ldC + col + 1]       = acc[mi][ni][1] * alpha + b1;
                C[(size_t)(row + 8) * ldC + col]     = acc[mi][ni][2] * alpha + b0;
                C[(size_t)(row + 8) * ldC + col + 1] = acc[mi][ni][3] * alpha + b1;
            }
    } else if (EPI == 1) {
        #pragma unroll
        for (int mi = 0; mi < 2; mi++)
            #pragma unroll
            for (int ni = 0; ni < 8; ni++) {
                int row = m0 + m0w + mi * 16 + (lane >> 2);
                int col = n0 + n0w + ni * 8 + ((lane & 3) << 1);
                float b0 = bias ? __ldg(bias + col) : 0.0f;
                float b1 = bias ? __ldg(bias + col + 1) : 0.0f;
                int h = col >> 6, d = col & 63;
                #pragma unroll
                for (int rr = 0; rr < 2; rr++) {
                    int r = row + rr * 8;
                    int b = r >> 11, s = r & 2047;
                    size_t o = ((((size_t)(b * 16 + h)) * S_ + s) * D_ + d) >> 1;
                    store_hl_h2(Ohi, Olo, o,
                                acc[mi][ni][rr * 2 + 0] + b0,
                                acc[mi][ni][rr * 2 + 1] + b1);
                }
            }
    } else {
        // EPI == 4: row-sum partials of exp(alpha*acc); no C write
        __shared__ float ps_s[128][2];
        float rs[2][2] = {{0.0f, 0.0f}, {0.0f, 0.0f}};
        #pragma unroll
        for (int mi = 0; mi < 2; mi++)
            #pragma unroll
            for (int ni = 0; ni < 8; ni++) {
                rs[mi][0] += fast_exp(acc[mi][ni][0] * alpha)
                           + fast_exp(acc[mi][ni][1] * alpha);
                rs[mi][1] += fast_exp(acc[mi][ni][2] * alpha)
                           + fast_exp(acc[mi][ni][3] * alpha);
            }
        #pragma unroll
        for (int mi = 0; mi < 2; mi++)
            #pragma unroll
            for (int rr = 0; rr < 2; rr++) {
                float v = rs[mi][rr];
                v += __shfl_xor_sync(0xFFFFFFFFu, v, 1);
                v += __shfl_xor_sync(0xFFFFFFFFu, v, 2);
                rs[mi][rr] = v;
            }
        if ((lane & 3) == 0) {
            #pragma unroll
            for (int mi = 0; mi < 2; mi++)
                #pragma unroll
                for (int rr = 0; rr < 2; rr++)
                    ps_s[m0w + mi * 16 + (lane >> 2) + rr * 8][wid & 1] = rs[mi][rr];
        }
        __syncthreads();
        if (tid < 128) {
            size_t o = ((size_t)z * gridDim.x + blockIdx.x) * (size_t)S_ + m0 + tid;
            gps[o] = ps_s[tid][0] + ps_s[tid][1];
        }
    }
}

// ---------------- combine: rinv = 1 / sum of 16 col-block partials -------
__global__ __launch_bounds__(256) void combine_kernel(
    const float* __restrict__ gps, float* __restrict__ rinv)
{
    int g = blockIdx.x * 256 + threadIdx.x;
    int bh = g >> 11, r = g & 2047;
    const float* ps = gps + (size_t)bh * 16 * S_ + r;
    float s = 0.0f;
    #pragma unroll
    for (int jb = 0; jb < 16; jb++) s += ps[(size_t)jb * S_];
    rinv[g] = 1.0f / s;
}

// ================= flash attention: QK recompute + P write + AV ==========
// V is 1-term fp16.  RACE FIX: load_kv(j+1) is issued AFTER the stage-ready
// __syncthreads, so writes to stage !st cannot overlap iter j-1's reads.
// smem: Q 20480 | K 2st x (hi/lo x 10240) = 40960 | V 2st x 10240 | P 20480
#define FA_Q0   0
#define FA_K0   20480
#define FA_V0   61440
#define FA_P0   81920
#define FA_SMEM 102400
__global__ __launch_bounds__(256, 2) void flash_av_kernel(
    const __half* __restrict__ qh,
    const __half* __restrict__ khi, const __half* __restrict__ klo,
    const __half* __restrict__ vthi,
    const float* __restrict__ rinv, float* __restrict__ Wbuf,
    __half* __restrict__ ctxh)
{
    extern __shared__ __align__(16) char smem[];
    const uint32_t sbase = smem_u32(smem);
    __shared__ float s_r[128];

    const int tid  = threadIdx.x;
    const int lane = tid & 31;
    const int wid  = tid >> 5;
    const int m0w  = (wid >> 1) * 32;
    const int n0w  = (wid & 1) * 32;
    const int i0   = blockIdx.x * 128;
    const int bh   = blockIdx.y;
    const int bb   = bh >> 4, hh = bh & 15;

    if (tid < 128) s_r[tid] = rinv[(size_t)bh * S_ + i0 + tid];

    const __half* qg = qh + ((size_t)bh * S_ + i0) * D_;
    #pragma unroll
    for (int l = 0; l < 4; l++) {
        int c = tid + l * 256;
        int it = c >> 9, cc = c & 511, r = cc >> 2, seg = cc & 3;
        cp16(sbase + FA_Q0 + it * 10240 + r * 80 + seg * 16,
             qg + (size_t)r * D_ + it * 32 + seg * 8);
    }
    auto load_kv = [&](int j) {
        const int st = j & 1, j0 = j * 64;
        #pragma unroll
        for (int l = 0; l < 4; l++) {
            int c = tid + l * 256;
            int t = c >> 9, cc = c & 511;
            int r = cc >> 3, rem = cc & 7, ch = rem >> 2, seg = rem & 3;
            const __half* src = (t ? klo : khi)
                + ((size_t)bh * S_ + j0 + r) * D_ + ch * 32 + seg * 8;
            cp16(sbase + FA_K0 + st * 20480 + t * 10240 + ch * 5120
                 + r * 80 + seg * 16, src);
        }
        #pragma unroll
        for (int l = 0; l < 2; l++) {
            int c = tid + l * 256;
            int r = c >> 3, rem = c & 7, ch = rem >> 2, seg = rem & 3;
            const __half* src = vthi
                + ((size_t)bh * D_ + r) * S_ + j0 + ch * 32 + seg * 8;
            cp16(sbase + FA_V0 + st * 10240 + ch * 5120
                 + r * 80 + seg * 16, src);
        }
    };
    load_kv(0);
    asm volatile("cp.async.commit_group;" ::: "memory");

    float ctx[2][4][4];
    #pragma unroll
    for (int a = 0; a < 2; a++)
        #pragma unroll
        for (int b = 0; b < 4; b++)
            #pragma unroll
            for (int q = 0; q < 4; q++) ctx[a][b][q] = 0.0f;

    for (int j = 0; j < 32; j++) {
        const int st = j & 1, j0 = j * 64;
        // stage st data ready; barrier also closes all stage-!st reads (iter j-1)
        asm volatile("cp.async.wait_group 0;" ::: "memory");
        __syncthreads();
        if (j + 1 < 32) {       // safe: after the barrier above
            load_kv(j + 1);
            asm volatile("cp.async.commit_group;" ::: "memory");
        }

        // ---- QK: s = q . k (K 2-term) ----
        float accs[2][4][4];
        #pragma unroll
        for (int a = 0; a < 2; a++)
            #pragma unroll
            for (int b = 0; b < 4; b++)
                #pragma unroll
                for (int q = 0; q < 4; q++) accs[a][b][q] = 0.0f;
        #pragma unroll
        for (int it = 0; it < 2; it++) {
            #pragma unroll
            for (int kk = 0; kk < 2; kk++) {
                uint32_t ah[2][4];
                #pragma unroll
                for (int mi = 0; mi < 2; mi++) {
                    uint32_t addr = sbase + FA_Q0 + it * 10240
                        + ((m0w + mi * 16 + (lane & 15)) * 40
                           + kk * 16 + ((lane >> 4) << 3)) * 2;
                    LDSM4(ah[mi], addr);
                }
                uint32_t bhf[4][2], blf[4][2];
                #pragma unroll
                for (int nj = 0; nj < 2; nj++) {
                    uint32_t row = n0w + nj * 16 + (lane & 7) + ((lane >> 4) << 3);
                    uint32_t col = kk * 16 + (((lane >> 3) & 1) << 3);
                    uint32_t addr = sbase + FA_K0 + st * 20480 + it * 5120
                        + (row * 40 + col) * 2;
                    uint32_t t4[4];
                    LDSM4(t4, addr);
                    bhf[2 * nj][0] = t4[0]; bhf[2 * nj][1] = t4[1];
                    bhf[2 * nj + 1][0] = t4[2]; bhf[2 * nj + 1][1] = t4[3];
                    LDSM4(t4, addr + 10240);
                    blf[2 * nj][0] = t4[0]; blf[2 * nj][1] = t4[1];
                    blf[2 * nj + 1][0] = t4[2]; blf[2 * nj + 1][1] = t4[3];
                }
                #pragma unroll
                for (int mi = 0; mi < 2; mi++)
                    #pragma unroll
                    for (int ni = 0; ni < 4; ni++) {
                        MMA_F16(accs[mi][ni], ah[mi], bhf[ni][0], bhf[ni][1]);
                        MMA_F16(accs[mi][ni], ah[mi], blf[ni][0], blf[ni][1]);
                    }
            }
        }

        // ---- P: p = exp(0.125 s) * rinv; write weights + fp16 P smem ----
        #pragma unroll
        for (int mi = 0; mi < 2; mi++)
            #pragma unroll
            for (int ni = 0; ni < 4; ni++) {
                int row0 = m0w + mi * 16 + (lane >> 2);
                int col  = n0w + ni * 8 + ((lane & 3) << 1);
                #pragma unroll
                for (int rr = 0; rr < 2; rr++) {
                    int row = row0 + rr * 8;
                    float p0 = fast_exp(accs[mi][ni][rr * 2 + 0] * 0.125f) * s_r[row];
                    float p1 = fast_exp(accs[mi][ni][rr * 2 + 1] * 0.125f) * s_r[row];
                    float2 w2; w2.x = p0; w2.y = p1;
                    *(float2*)(Wbuf + ((size_t)bh * S_ + i0 + row) * S_ + j0 + col) = w2;
                    __half2 hp = __floats2half2_rn(p0, p1);
                    int ch = col >> 5, c32 = col & 31;
                    *(uint32_t*)(smem + FA_P0 + ch * 10240 + row * 80 + c32 * 2)
                        = *(uint32_t*)&hp;
                }
            }
        __syncthreads();

        // ---- AV: ctx += p . v (V 1-term) ----
        #pragma unroll
        for (int it = 0; it < 2; it++) {
            #pragma unroll
            for (int kk = 0; kk < 2; kk++) {
                uint32_t ah[2][4];
                #pragma unroll
                for (int mi = 0; mi < 2; mi++) {
                    uint32_t addr = sbase + FA_P0 + it * 10240
                        + ((m0w + mi * 16 + (lane & 15)) * 40
                           + kk * 16 + ((lane >> 4) << 3)) * 2;
                    LDSM4(ah[mi], addr);
                }
                uint32_t bhf[4][2];
                #pragma unroll
                for (int nj = 0; nj < 2; nj++) {
                    uint32_t row = n0w + nj * 16 + (lane & 7) + ((lane >> 4) << 3);
                    uint32_t col = kk * 16 + (((lane >> 3) & 1) << 3);
                    uint32_t addr = sbase + FA_V0 + st * 10240 + it * 5120
                        + (row * 40 + col) * 2;
                    uint32_t t4[4];
                    LDSM4(t4, addr);
                    bhf[2 * nj][0] = t4[0]; bhf[2 * nj][1] = t4[1];
                    bhf[2 * nj + 1][0] = t4[2]; bhf[2 * nj + 1][1] = t4[3];
                }
                #pragma unroll
                for (int mi = 0; mi < 2; mi++)
                    #pragma unroll
                    for (int ni = 0; ni < 4; ni++)
                        MMA_F16(ctx[mi][ni], ah[mi], bhf[ni][0], bhf[ni][1]);
            }
        }
    }

    #pragma unroll
    for (int mi = 0; mi < 2; mi++)
        #pragma unroll
        for (int ni = 0; ni < 4; ni++) {
            int row0 = m0w + mi * 16 + (lane >> 2);
            int col  = n0w + ni * 8 + ((lane & 3) << 1);
            #pragma unroll
            for (int rr = 0; rr < 2; rr++) {
                int row = row0 + rr * 8;
                size_t token = (size_t)bb * S_ + i0 + row;
                size_t o = (token * E_ + hh * 64 + col) >> 1;
                ((__half2*)ctxh)[o] =
                    __floats2half2_rn(ctx[mi][ni][rr * 2 + 0],
                                      ctx[mi][ni][rr * 2 + 1]);
            }
        }
}

// ================= conversions ===========================================
__global__ __launch_bounds__(256) void conv_h4_kernel(
    const float4* __restrict__ in, __half2* __restrict__ out, int n4)
{
    int i = blockIdx.x * 256 + threadIdx.x;
    if (i < n4) {
        float4 v = in[i];
        out[2 * i]     = __floats2half2_rn(v.x, v.y);
        out[2 * i + 1] = __floats2half2_rn(v.z, v.w);
    }
}

// W[K,N] fp32 -> Wt[N,K] fp16 hi/lo (lo optional)
__global__ __launch_bounds__(256) void transconv_h_kernel(
    const float* __restrict__ W, __half* __restrict__ hi,
    __half* __restrict__ lo, int K, int N)
{
    __shared__ float t[32][33];
    const int k0 = blockIdx.y * 32, n0 = blockIdx.x * 32;
    const int tx = threadIdx.x & 31, ty = threadIdx.x >> 5;
    #pragma unroll
    for (int i = 0; i < 32; i += 8)
        t[ty + i][tx] = W[(size_t)(k0 + ty + i) * N + n0 + tx];
    __syncthreads();
    #pragma unroll
    for (int i = 0; i < 32; i += 8) {
        float x = t[tx][ty + i];
        __half h = __float2half_rn(x);
        size_t o = (size_t)(n0 + ty + i) * K + k0 + tx;
        hi[o] = h;
        if (lo) lo[o] = __float2half_rn(x - __half2float(h));
    }
}

// [bh][s][d] 16-bit -> [bh][d][s] 16-bit (single array)
__global__ __launch_bounds__(256) void transpose16_kernel(
    const uint16_t* __restrict__ in, uint16_t* __restrict__ outp)
{
    __shared__ uint16_t th[32][33];
    const int bh = blockIdx.z;
    const int s0 = blockIdx.x * 32, d0 = blockIdx.y * 32;
    const int tx = threadIdx.x & 31, ty = threadIdx.x >> 5;
    #pragma unroll
    for (int i = 0; i < 32; i += 8)
        th[ty + i][tx] = in[((size_t)bh * S_ + s0 + ty + i) * D_ + d0 + tx];
    __syncthreads();
    #pragma unroll
    for (int i = 0; i < 32; i += 8)
        outp[((size_t)bh * D_ + d0 + ty + i) * S_ + s0 + tx] = th[tx][ty + i];
}

// ---------------- launch ----------------
extern "C" void kernel_launch(void* const* d_in, const int* in_sizes, int n_in,
                              void* d_out, int out_size)
{
    const float* query = (const float*)d_in[0];
    const float* key   = (const float*)d_in[1];
    const float* value = (const float*)d_in[2];
    const float* Wq    = (const float*)d_in[3];
    const float* bq    = (const float*)d_in[4];
    const float* Wk    = (const float*)d_in[5];
    const float* bk    = (const float*)d_in[6];
    const float* Wv    = (const float*)d_in[7];
    const float* bv    = (const float*)d_in[8];
    const float* Wo    = (const float*)d_in[9];
    const float* bo    = (const float*)d_in[10];

    float* out  = (float*)d_out;                 // [B,S,E]
    float* Wbuf = out + (size_t)M_ * E_;         // [B,H,S,S]

    __half *ahf, *wohi, *wolo, *qhi, *khi, *klo, *vhi, *vthi, *ctxh;
    float *gps, *gri;
    cudaGetSymbolAddress((void**)&ahf,  g_Ahf);
    cudaGetSymbolAddress((void**)&wohi, g_Wohi);
    cudaGetSymbolAddress((void**)&wolo, g_Wolo);
    cudaGetSymbolAddress((void**)&qhi,  g_qhi);
    cudaGetSymbolAddress((void**)&khi,  g_khi);
    cudaGetSymbolAddress((void**)&klo,  g_klo);
    cudaGetSymbolAddress((void**)&vhi,  g_vhi);
    cudaGetSymbolAddress((void**)&vthi, g_vthi);
    cudaGetSymbolAddress((void**)&ctxh, g_ctxh);
    cudaGetSymbolAddress((void**)&gps,  g_psum);
    cudaGetSymbolAddress((void**)&gri,  g_rinv);

    const int SMEM_G2 = 2 * (128 * 80 + 2 * 128 * 80);  // 61440 (2-term)
    const int SMEM_G1 = 2 * (128 * 80 + 1 * 128 * 80);  // 40960 (1-term)
    cudaFuncSetAttribute(h2term_gemm<0, 1>,
                         cudaFuncAttributeMaxDynamicSharedMemorySize, SMEM_G1);
    cudaFuncSetAttribute(h2term_gemm<1, 2>,
                         cudaFuncAttributeMaxDynamicSharedMemorySize, SMEM_G2);
    cudaFuncSetAttribute(h2term_gemm<4, 1>,
                         cudaFuncAttributeMaxDynamicSharedMemorySize, SMEM_G1);
    cudaFuncSetAttribute(flash_av_kernel,
                         cudaFuncAttributeMaxDynamicSharedMemorySize, FA_SMEM);

    // ---- projections (fp16 2-term, write head-major fp16) ----
    conv_h4_kernel<<<(M_ * QD_ / 4 + 255) / 256, 256>>>(
        (const float4*)query, (__half2*)ahf, M_ * QD_ / 4);
    transconv_h_kernel<<<dim3(E_ / 32, QD_ / 32), 256>>>(Wq, wohi, wolo, QD_, E_);
    h2term_gemm<1, 2><<<dim3(E_ / 128, M_ / 128, 1), 256, SMEM_G2>>>(
        ahf, wohi, wolo, bq, nullptr, qhi, nullptr, nullptr,
        QD_, QD_, QD_, E_, 0, 0, 0, 1.0f);

    conv_h4_kernel<<<(M_ * KD_ / 4 + 255) / 256, 256>>>(
        (const float4*)key, (__half2*)ahf, M_ * KD_ / 4);
    transconv_h_kernel<<<dim3(E_ / 32, KD_ / 32), 256>>>(Wk, wohi, wolo, KD_, E_);
    h2term_gemm<1, 2><<<dim3(E_ / 128, M_ / 128, 1), 256, SMEM_G2>>>(
        ahf, wohi, wolo, bk, nullptr, khi, klo, nullptr,
        KD_, KD_, KD_, E_, 0, 0, 0, 1.0f);

    conv_h4_kernel<<<(M_ * VD_ / 4 + 255) / 256, 256>>>(
        (const float4*)value, (__half2*)ahf, M_ * VD_ / 4);
    transconv_h_kernel<<<dim3(E_ / 32, VD_ / 32), 256>>>(Wv, wohi, wolo, VD_, E_);
    h2term_gemm<1, 2><<<dim3(E_ / 128, M_ / 128, 1), 256, SMEM_G2>>>(
        ahf, wohi, wolo, bv, nullptr, vhi, nullptr, nullptr,
        VD_, VD_, VD_, E_, 0, 0, 0, 1.0f);

    transpose16_kernel<<<dim3(S_ / 32, D_ / 32, BH_), 256>>>(
        (const uint16_t*)vhi, (uint16_t*)vthi);

    // ---- pass 1: row-sum stats only (1-term K) ----
    h2term_gemm<4, 1><<<dim3(S_ / 128, S_ / 128, BH_), 256, SMEM_G1>>>(
        qhi, khi, nullptr, nullptr, nullptr, nullptr, nullptr, gps,
        D_, D_, D_, S_,
        (long long)S_ * D_, (long long)S_ * D_, 0, 0.125f);

    combine_kernel<<<(BH_ * S_) / 256, 256>>>(gps, gri);

    // ---- pass 2: fused QK recompute + weights write + AV (V 1-term) ----
    flash_av_kernel<<<dim3(S_ / 128, BH_), 256, FA_SMEM>>>(
        qhi, khi, klo, vthi, gri, Wbuf, ctxh);

    // ---- output projection (1-term Wo) ----
    transconv_h_kernel<<<dim3(E_ / 32, E_ / 32), 256>>>(Wo, wohi, nullptr, E_, E_);
    h2term_gemm<0, 1><<<dim3(E_ / 128, M_ / 128, 1), 256, SMEM_G1>>>(
        ctxh, wohi, nullptr, bo, out, nullptr, nullptr, nullptr,
        E_, E_, E_, E_, 0, 0, 0, 1.0f);
}